// round 1
// baseline (speedup 1.0000x reference)
#include <cuda_runtime.h>
#include <cuda_bf16.h>
#include <cstdint>

#define GN 50000      // nodes
#define GE 800000     // edges (without self loops)
#define GIN 256       // in_dim
#define GH 8          // heads layer1
#define GHID 32       // hidden per head
#define GF1 256       // H*HID
#define GOUT 64       // classes

// ---------------- scratch (device globals; no allocations allowed) -------------
__device__ float g_h1[(size_t)GN * GF1];    // x @ W1
__device__ float g_out1[(size_t)GN * GF1];  // relu(gat1 out)
__device__ float g_h2[(size_t)GN * GOUT];   // out1 @ W2
__device__ float g_as1[(size_t)GN * GH];
__device__ float g_ad1[(size_t)GN * GH];
__device__ float g_as2[GN];
__device__ float g_ad2[GN];
__device__ int   g_cnt[GN];        // histogram -> cursor
__device__ int   g_rowptr[GN + 1];
__device__ int   g_srcs[GE];       // src ids bucketed by dst

__device__ __forceinline__ float lrelu(float x) { return fmaxf(x, 0.2f * x); }

// ---------------- CSR build ----------------------------------------------------
__global__ void zero_cnt_kernel() {
    int i = blockIdx.x * blockDim.x + threadIdx.x;
    if (i < GN) g_cnt[i] = 0;
}

__global__ void hist_kernel(const int* __restrict__ ei, int E) {
    int e = blockIdx.x * blockDim.x + threadIdx.x;
    if (e < E) atomicAdd(&g_cnt[ei[E + e]], 1);
}

__global__ void scan_kernel(int n) {
    __shared__ int sh[1024];
    __shared__ int carry;
    if (threadIdx.x == 0) carry = 0;
    __syncthreads();
    for (int base = 0; base < n; base += 1024) {
        int i = base + threadIdx.x;
        int v = (i < n) ? g_cnt[i] : 0;
        sh[threadIdx.x] = v;
        __syncthreads();
        #pragma unroll
        for (int off = 1; off < 1024; off <<= 1) {
            int t = (threadIdx.x >= off) ? sh[threadIdx.x - off] : 0;
            __syncthreads();
            sh[threadIdx.x] += t;
            __syncthreads();
        }
        int incl = sh[threadIdx.x] + carry;
        if (i < n) {
            g_rowptr[i + 1] = incl;
            g_cnt[i] = incl - v;   // exclusive prefix -> scatter cursor
        }
        __syncthreads();
        if (threadIdx.x == 1023) carry = incl;
        __syncthreads();
    }
    if (threadIdx.x == 0) g_rowptr[0] = 0;
}

__global__ void scatter_kernel(const int* __restrict__ ei, int E) {
    int e = blockIdx.x * blockDim.x + threadIdx.x;
    if (e < E) {
        int dst = ei[E + e];
        int pos = atomicAdd(&g_cnt[dst], 1);
        g_srcs[pos] = ei[e];
    }
}

// ---------------- SGEMM (C = A[MxK] * B[KxN], all row-major) -------------------
template <int BM, int BN, int BK, int TM, int TN>
__global__ void sgemm_kernel(const float* __restrict__ A, const float* __restrict__ B,
                             float* __restrict__ C, int M, int K, int Nc) {
    constexpr int THREADS = (BM / TM) * (BN / TN);
    __shared__ float As[BK][BM];
    __shared__ float Bs[BK][BN];
    const int tid = threadIdx.x;
    constexpr int TX = BN / TN;
    const int tx = tid % TX;
    const int ty = tid / TX;
    const int rowBase = blockIdx.y * BM;
    const int colBase = blockIdx.x * BN;

    float acc[TM][TN];
    #pragma unroll
    for (int i = 0; i < TM; i++)
        #pragma unroll
        for (int j = 0; j < TN; j++) acc[i][j] = 0.f;

    for (int k0 = 0; k0 < K; k0 += BK) {
        constexpr int A_LOADS = BM * BK / 4 / THREADS;
        #pragma unroll
        for (int i = 0; i < A_LOADS; i++) {
            int lin = tid + i * THREADS;
            int r = lin / (BK / 4);
            int kq = lin % (BK / 4);
            float4 v = make_float4(0.f, 0.f, 0.f, 0.f);
            int row = rowBase + r;
            if (row < M)
                v = *reinterpret_cast<const float4*>(A + (size_t)row * K + k0 + kq * 4);
            As[kq * 4 + 0][r] = v.x;
            As[kq * 4 + 1][r] = v.y;
            As[kq * 4 + 2][r] = v.z;
            As[kq * 4 + 3][r] = v.w;
        }
        constexpr int B_LOADS = BK * BN / 4 / THREADS;
        #pragma unroll
        for (int i = 0; i < B_LOADS; i++) {
            int lin = tid + i * THREADS;
            int r = lin / (BN / 4);
            int cq = lin % (BN / 4);
            float4 v = *reinterpret_cast<const float4*>(B + (size_t)(k0 + r) * Nc + colBase + cq * 4);
            *reinterpret_cast<float4*>(&Bs[r][cq * 4]) = v;
        }
        __syncthreads();
        #pragma unroll
        for (int k = 0; k < BK; k++) {
            float ra[TM], rb[TN];
            #pragma unroll
            for (int i = 0; i < TM; i++) ra[i] = As[k][ty * TM + i];
            #pragma unroll
            for (int j = 0; j < TN; j++) rb[j] = Bs[k][tx * TN + j];
            #pragma unroll
            for (int i = 0; i < TM; i++)
                #pragma unroll
                for (int j = 0; j < TN; j++) acc[i][j] += ra[i] * rb[j];
        }
        __syncthreads();
    }
    #pragma unroll
    for (int i = 0; i < TM; i++) {
        int row = rowBase + ty * TM + i;
        if (row < M) {
            #pragma unroll
            for (int j = 0; j < TN; j++)
                C[(size_t)row * Nc + colBase + tx * TN + j] = acc[i][j];
        }
    }
}

// ---------------- attention coefficients ---------------------------------------
__global__ void alpha1_kernel(const float* __restrict__ a_src, const float* __restrict__ a_dst) {
    int t = blockIdx.x * blockDim.x + threadIdx.x;
    if (t >= GN * GH) return;
    int node = t >> 3;
    int h = t & 7;
    const float* hp = g_h1 + (size_t)node * GF1 + h * GHID;
    const float* as = a_src + h * GHID;
    const float* ad = a_dst + h * GHID;
    float s1 = 0.f, s2 = 0.f;
    #pragma unroll
    for (int c = 0; c < GHID; c++) {
        float v = hp[c];
        s1 += v * as[c];
        s2 += v * ad[c];
    }
    g_as1[t] = s1;
    g_ad1[t] = s2;
}

__global__ void alpha2_kernel(const float* __restrict__ a_src, const float* __restrict__ a_dst) {
    int warp = (blockIdx.x * blockDim.x + threadIdx.x) >> 5;
    int lane = threadIdx.x & 31;
    if (warp >= GN) return;
    float v0 = g_h2[(size_t)warp * GOUT + lane];
    float v1 = g_h2[(size_t)warp * GOUT + 32 + lane];
    float s = v0 * a_src[lane] + v1 * a_src[32 + lane];
    float d = v0 * a_dst[lane] + v1 * a_dst[32 + lane];
    #pragma unroll
    for (int o = 16; o; o >>= 1) {
        s += __shfl_xor_sync(0xffffffffu, s, o);
        d += __shfl_xor_sync(0xffffffffu, d, o);
    }
    if (lane == 0) {
        g_as2[warp] = s;
        g_ad2[warp] = d;
    }
}

// ---------------- layer-1 aggregation (warp per dst) ---------------------------
__global__ void __launch_bounds__(256) agg1_kernel(const float* __restrict__ b1) {
    int dst = (blockIdx.x * blockDim.x + threadIdx.x) >> 5;
    int lane = threadIdx.x & 31;
    if (dst >= GN) return;

    float ad[GH];
    #pragma unroll
    for (int h = 0; h < GH; h++) ad[h] = g_ad1[(size_t)dst * GH + h];  // uniform -> broadcast

    const int rs = g_rowptr[dst];
    const int re = g_rowptr[dst + 1];

    // ---- pass A: per-head max over incoming edges + self loop (lane-parallel)
    float mx[GH];
    #pragma unroll
    for (int h = 0; h < GH; h++) mx[h] = lrelu(g_as1[(size_t)dst * GH + h] + ad[h]);
    for (int e = rs + lane; e < re; e += 32) {
        int src = g_srcs[e];
        const float4* ap = reinterpret_cast<const float4*>(g_as1 + (size_t)src * GH);
        float4 a0 = ap[0], a1 = ap[1];
        float av[GH] = {a0.x, a0.y, a0.z, a0.w, a1.x, a1.y, a1.z, a1.w};
        #pragma unroll
        for (int h = 0; h < GH; h++) mx[h] = fmaxf(mx[h], lrelu(av[h] + ad[h]));
    }
    #pragma unroll
    for (int o = 16; o; o >>= 1)
        #pragma unroll
        for (int h = 0; h < GH; h++) mx[h] = fmaxf(mx[h], __shfl_xor_sync(0xffffffffu, mx[h], o));

    // ---- pass B: denom + weighted feature accumulation (warp-cooperative)
    float acc[GH], den[GH];
    {   // self loop
        const float* hp = g_h1 + (size_t)dst * GF1;
        #pragma unroll
        for (int h = 0; h < GH; h++) {
            float w = __expf(lrelu(g_as1[(size_t)dst * GH + h] + ad[h]) - mx[h]);
            den[h] = w;
            acc[h] = w * hp[h * GHID + lane];
        }
    }
    for (int e = rs; e < re; e++) {
        int src = g_srcs[e];                       // uniform load -> broadcast
        const float4* ap = reinterpret_cast<const float4*>(g_as1 + (size_t)src * GH);
        float4 a0 = ap[0], a1 = ap[1];
        float av[GH] = {a0.x, a0.y, a0.z, a0.w, a1.x, a1.y, a1.z, a1.w};
        const float* hp = g_h1 + (size_t)src * GF1;
        #pragma unroll
        for (int h = 0; h < GH; h++) {
            float w = __expf(lrelu(av[h] + ad[h]) - mx[h]);
            den[h] += w;
            acc[h] += w * hp[h * GHID + lane];     // 128B coalesced per head
        }
    }
    #pragma unroll
    for (int h = 0; h < GH; h++) {
        float v = acc[h] / den[h] + b1[h * GHID + lane];
        g_out1[(size_t)dst * GF1 + h * GHID + lane] = fmaxf(v, 0.f);   // relu fused
    }
}

// ---------------- layer-2 aggregation + bias + log_softmax (warp per dst) ------
__global__ void __launch_bounds__(256) agg2_kernel(const float* __restrict__ b2,
                                                   float* __restrict__ out) {
    int dst = (blockIdx.x * blockDim.x + threadIdx.x) >> 5;
    int lane = threadIdx.x & 31;
    if (dst >= GN) return;

    const float ad = g_ad2[dst];
    const int rs = g_rowptr[dst];
    const int re = g_rowptr[dst + 1];

    float mx = lrelu(g_as2[dst] + ad);
    for (int e = rs + lane; e < re; e += 32)
        mx = fmaxf(mx, lrelu(g_as2[g_srcs[e]] + ad));
    #pragma unroll
    for (int o = 16; o; o >>= 1) mx = fmaxf(mx, __shfl_xor_sync(0xffffffffu, mx, o));

    float den, a0, a1;
    {
        float w = __expf(lrelu(g_as2[dst] + ad) - mx);
        den = w;
        a0 = w * g_h2[(size_t)dst * GOUT + lane];
        a1 = w * g_h2[(size_t)dst * GOUT + 32 + lane];
    }
    for (int e = rs; e < re; e++) {
        int src = g_srcs[e];
        float w = __expf(lrelu(g_as2[src] + ad) - mx);
        den += w;
        a0 += w * g_h2[(size_t)src * GOUT + lane];
        a1 += w * g_h2[(size_t)src * GOUT + 32 + lane];
    }
    float v0 = a0 / den + b2[lane];
    float v1 = a1 / den + b2[32 + lane];

    float m = fmaxf(v0, v1);
    #pragma unroll
    for (int o = 16; o; o >>= 1) m = fmaxf(m, __shfl_xor_sync(0xffffffffu, m, o));
    float s = __expf(v0 - m) + __expf(v1 - m);
    #pragma unroll
    for (int o = 16; o; o >>= 1) s += __shfl_xor_sync(0xffffffffu, s, o);
    float ls = __logf(s);

    out[(size_t)dst * GOUT + lane] = v0 - m - ls;
    out[(size_t)dst * GOUT + 32 + lane] = v1 - m - ls;
}

// ---------------- launch --------------------------------------------------------
extern "C" void kernel_launch(void* const* d_in, const int* in_sizes, int n_in,
                              void* d_out, int out_size) {
    const float* x      = (const float*)d_in[0];
    const int*   ei     = (const int*)d_in[1];
    const float* W1     = (const float*)d_in[2];
    const float* a_src1 = (const float*)d_in[3];
    const float* a_dst1 = (const float*)d_in[4];
    const float* b1     = (const float*)d_in[5];
    const float* W2     = (const float*)d_in[6];
    const float* a_src2 = (const float*)d_in[7];
    const float* a_dst2 = (const float*)d_in[8];
    const float* b2     = (const float*)d_in[9];
    float* out = (float*)d_out;
    const int E = in_sizes[1] / 2;

    float *h1p, *out1p, *h2p;
    cudaGetSymbolAddress((void**)&h1p, g_h1);
    cudaGetSymbolAddress((void**)&out1p, g_out1);
    cudaGetSymbolAddress((void**)&h2p, g_h2);

    // CSR build
    zero_cnt_kernel<<<(GN + 255) / 256, 256>>>();
    hist_kernel<<<(E + 255) / 256, 256>>>(ei, E);
    scan_kernel<<<1, 1024>>>(GN);
    scatter_kernel<<<(E + 255) / 256, 256>>>(ei, E);

    // layer 1
    sgemm_kernel<128, 64, 16, 8, 4>
        <<<dim3(GF1 / 64, (GN + 127) / 128), 256>>>(x, W1, h1p, GN, GIN, GF1);
    alpha1_kernel<<<(GN * GH + 255) / 256, 256>>>(a_src1, a_dst1);
    agg1_kernel<<<(GN + 7) / 8, 256>>>(b1);

    // layer 2
    sgemm_kernel<128, 64, 16, 8, 4>
        <<<dim3(GOUT / 64, (GN + 127) / 128), 256>>>(out1p, W2, h2p, GN, GF1, GOUT);
    alpha2_kernel<<<(GN + 7) / 8, 256>>>(a_src2, a_dst2);
    agg2_kernel<<<(GN + 7) / 8, 256>>>(b2, out);
}

// round 3
// speedup vs baseline: 1.5602x; 1.5602x over previous
#include <cuda_runtime.h>
#include <cuda_bf16.h>
#include <cstdint>

#define GN 50000      // nodes
#define GE 800000     // edges (without self loops)
#define GIN 256       // in_dim
#define GH 8          // heads layer1
#define GHID 32       // hidden per head
#define GF1 256       // H*HID
#define GOUT 64       // classes

// ---------------- scratch (device globals; no allocations allowed) -------------
__device__ float g_h1[(size_t)GN * GF1];    // x @ W1
__device__ float g_out1[(size_t)GN * GF1];  // relu(gat1 out)
__device__ float g_h2[(size_t)GN * GOUT];   // out1 @ W2
__device__ float g_as1[(size_t)GN * GH];
__device__ float g_ad1[(size_t)GN * GH];
__device__ float g_as2[GN];
__device__ float g_ad2[GN];
__device__ int   g_cnt[GN];        // histogram -> cursor
__device__ int   g_rowptr[GN + 1];
__device__ int   g_srcs[GE];       // src ids bucketed by dst

__device__ __forceinline__ float lrelu(float x) { return fmaxf(x, 0.2f * x); }

__device__ __forceinline__ uint32_t f2tf32(float f) {
    uint32_t u;
    asm("cvt.rna.tf32.f32 %0, %1;" : "=r"(u) : "f"(f));
    return u;
}

__device__ __forceinline__ void mma_tf32(float* c, uint32_t a0, uint32_t a1,
                                         uint32_t a2, uint32_t a3,
                                         uint32_t b0, uint32_t b1) {
    asm volatile(
        "mma.sync.aligned.m16n8k8.row.col.f32.tf32.tf32.f32 "
        "{%0,%1,%2,%3},{%4,%5,%6,%7},{%8,%9},{%0,%1,%2,%3};\n"
        : "+f"(c[0]), "+f"(c[1]), "+f"(c[2]), "+f"(c[3])
        : "r"(a0), "r"(a1), "r"(a2), "r"(a3), "r"(b0), "r"(b1));
}

// ---------------- CSR build ----------------------------------------------------
__global__ void hist_kernel(const int* __restrict__ ei, int E) {
    int e = blockIdx.x * blockDim.x + threadIdx.x;
    if (e < E) atomicAdd(&g_cnt[ei[E + e]], 1);
}

__global__ void scan_kernel(int n) {
    __shared__ int sums[32];
    __shared__ int carry_sh;
    const int tid = threadIdx.x, lane = tid & 31, wid = tid >> 5;
    if (tid == 0) carry_sh = 0;
    __syncthreads();
    for (int base = 0; base < n; base += 1024) {
        int carry = carry_sh;
        int i = base + tid;
        int v = (i < n) ? g_cnt[i] : 0;
        int s = v;
        #pragma unroll
        for (int o = 1; o < 32; o <<= 1) {
            int t = __shfl_up_sync(0xffffffffu, s, o);
            if (lane >= o) s += t;
        }
        if (lane == 31) sums[wid] = s;
        __syncthreads();
        if (wid == 0) {
            int t = sums[lane];
            #pragma unroll
            for (int o = 1; o < 32; o <<= 1) {
                int u = __shfl_up_sync(0xffffffffu, t, o);
                if (lane >= o) t += u;
            }
            sums[lane] = t;
        }
        __syncthreads();
        int off = (wid > 0) ? sums[wid - 1] : 0;
        int incl = carry + off + s;
        if (i < n) {
            g_rowptr[i + 1] = incl;
            g_cnt[i] = incl - v;   // exclusive prefix -> scatter cursor
        }
        __syncthreads();
        if (tid == 0) carry_sh = carry + sums[31];
        __syncthreads();
    }
    if (tid == 0) g_rowptr[0] = 0;
}

__global__ void scatter_kernel(const int* __restrict__ ei, int E) {
    int e = blockIdx.x * blockDim.x + threadIdx.x;
    if (e < E) {
        int dst = ei[E + e];
        int pos = atomicAdd(&g_cnt[dst], 1);
        g_srcs[pos] = ei[e];
    }
}

// ---------------- TF32 tensor-core GEMM (row-major A,B,C) ----------------------
// BM=128, BK=32, 256 threads, warp grid 4(M) x 2(N). Fragments stored
// pre-permuted in shared so each thread frag = one LDS.128.
// FUSE: also computes alpha_src/alpha_dst per (row, head) (heads of 32 cols).
template <int BN, bool FUSE>
__global__ void __launch_bounds__(256) gemm_tf32_kernel(
    const float* __restrict__ A, const float* __restrict__ B,
    float* __restrict__ C, int M, int K, int Nc,
    const float* __restrict__ a_src, const float* __restrict__ a_dst,
    float* __restrict__ g_as, float* __restrict__ g_ad) {
    constexpr int NT = BN / 16;  // n-tile pairs total / warp n-tiles
    constexpr int NP = BN / 32;  // n-pairs per warp
    __shared__ uint32_t sA[4][8][32][4];
    __shared__ uint32_t sB[4][NT][32][4];

    const int tid = threadIdx.x, lane = tid & 31, wid = tid >> 5;
    const int warpM = wid & 3, warpN = wid >> 2;
    const int rowBase = blockIdx.y * 128;
    const int colBase = blockIdx.x * BN;
    const int wcb = colBase + warpN * (BN / 2);

    float c[2][NT][4];
    #pragma unroll
    for (int i = 0; i < 2; i++)
        #pragma unroll
        for (int j = 0; j < NT; j++)
            #pragma unroll
            for (int q = 0; q < 4; q++) c[i][j][q] = 0.f;

    for (int k0 = 0; k0 < K; k0 += 32) {
        if (k0) __syncthreads();
        // stage A: 128x32
        #pragma unroll
        for (int i = 0; i < 4; i++) {
            int f = tid + i * 256;
            int r = f >> 3;
            int kc = (f & 7) * 4;
            int row = rowBase + r;
            float4 v = make_float4(0.f, 0.f, 0.f, 0.f);
            if (row < M) v = *reinterpret_cast<const float4*>(A + (size_t)row * K + k0 + kc);
            float vv[4] = {v.x, v.y, v.z, v.w};
            int rr = r & 15, mt = r >> 4;
            #pragma unroll
            for (int j = 0; j < 4; j++) {
                int k = kc + j;
                int ks = k >> 3, cc = k & 7;
                int slot = ((cc >= 4) << 1) | ((rr >= 8) ? 1 : 0);
                sA[ks][mt][(rr & 7) * 4 + (cc & 3)][slot] = f2tf32(vv[j]);
            }
        }
        // stage B: 32xBN
        constexpr int BL = 32 * BN / 1024;
        #pragma unroll
        for (int i = 0; i < BL; i++) {
            int f = tid + i * 256;
            int krow = f / (BN / 4);
            int n0 = (f % (BN / 4)) * 4;
            float4 v = *reinterpret_cast<const float4*>(B + (size_t)(k0 + krow) * Nc + colBase + n0);
            float vv[4] = {v.x, v.y, v.z, v.w};
            int ks = krow >> 3, r = krow & 7;
            int half = (r >= 4) ? 1 : 0;
            #pragma unroll
            for (int j = 0; j < 4; j++) {
                int n = n0 + j;
                int l2 = ((n & 7) << 2) | (r & 3);
                int pair = (n & (BN - 1)) >> 4;
                int odd = (n >> 3) & 1;
                sB[ks][pair][l2][(odd << 1) | half] = f2tf32(vv[j]);
            }
        }
        __syncthreads();
        #pragma unroll
        for (int ks = 0; ks < 4; ks++) {
            uint4 av[2];
            av[0] = *reinterpret_cast<uint4*>(&sA[ks][warpM * 2 + 0][lane][0]);
            av[1] = *reinterpret_cast<uint4*>(&sA[ks][warpM * 2 + 1][lane][0]);
            uint4 bv[NP];
            #pragma unroll
            for (int np = 0; np < NP; np++)
                bv[np] = *reinterpret_cast<uint4*>(&sB[ks][warpN * NP + np][lane][0]);
            #pragma unroll
            for (int mt = 0; mt < 2; mt++)
                #pragma unroll
                for (int nt = 0; nt < NT; nt++) {
                    int np = nt >> 1;
                    uint32_t b0 = (nt & 1) ? bv[np].z : bv[np].x;
                    uint32_t b1 = (nt & 1) ? bv[np].w : bv[np].y;
                    mma_tf32(c[mt][nt], av[mt].x, av[mt].y, av[mt].z, av[mt].w, b0, b1);
                }
        }
    }

    // epilogue: store C
    #pragma unroll
    for (int mt = 0; mt < 2; mt++)
        #pragma unroll
        for (int half = 0; half < 2; half++) {
            int row = rowBase + warpM * 32 + mt * 16 + (lane >> 2) + half * 8;
            if (row < M) {
                #pragma unroll
                for (int nt = 0; nt < NT; nt++) {
                    int col = wcb + nt * 8 + (lane & 3) * 2;
                    float2 st = make_float2(c[mt][nt][half * 2], c[mt][nt][half * 2 + 1]);
                    *reinterpret_cast<float2*>(C + (size_t)row * Nc + col) = st;
                }
            }
        }

    if (FUSE) {
        // per-warp slice = BN/2 = 64 cols = 2 heads (32 cols each)
        float asc[NT * 2], adc[NT * 2];
        #pragma unroll
        for (int nt = 0; nt < NT; nt++)
            #pragma unroll
            for (int j = 0; j < 2; j++) {
                int col = wcb + nt * 8 + (lane & 3) * 2 + j;
                asc[nt * 2 + j] = a_src[col];   // [H][HID] flat == col
                adc[nt * 2 + j] = a_dst[col];
            }
        int headBase = wcb >> 5;
        #pragma unroll
        for (int mt = 0; mt < 2; mt++)
            #pragma unroll
            for (int half = 0; half < 2; half++) {
                int row = rowBase + warpM * 32 + mt * 16 + (lane >> 2) + half * 8;
                float ss0 = 0.f, ss1 = 0.f, sd0 = 0.f, sd1 = 0.f;
                #pragma unroll
                for (int nt = 0; nt < NT; nt++)
                    #pragma unroll
                    for (int j = 0; j < 2; j++) {
                        float v = c[mt][nt][half * 2 + j];
                        if (nt < NT / 2) { ss0 += v * asc[nt * 2 + j]; sd0 += v * adc[nt * 2 + j]; }
                        else             { ss1 += v * asc[nt * 2 + j]; sd1 += v * adc[nt * 2 + j]; }
                    }
                #pragma unroll
                for (int o = 1; o <= 2; o <<= 1) {
                    ss0 += __shfl_xor_sync(0xffffffffu, ss0, o);
                    ss1 += __shfl_xor_sync(0xffffffffu, ss1, o);
                    sd0 += __shfl_xor_sync(0xffffffffu, sd0, o);
                    sd1 += __shfl_xor_sync(0xffffffffu, sd1, o);
                }
                if ((lane & 3) == 0 && row < M) {
                    g_as[(size_t)row * GH + headBase]     = ss0;
                    g_as[(size_t)row * GH + headBase + 1] = ss1;
                    g_ad[(size_t)row * GH + headBase]     = sd0;
                    g_ad[(size_t)row * GH + headBase + 1] = sd1;
                }
            }
    }
}

// ---------------- alpha2 --------------------------------------------------------
__global__ void alpha2_kernel(const float* __restrict__ a_src, const float* __restrict__ a_dst) {
    int warp = (blockIdx.x * blockDim.x + threadIdx.x) >> 5;
    int lane = threadIdx.x & 31;
    if (warp >= GN) return;
    float v0 = g_h2[(size_t)warp * GOUT + lane];
    float v1 = g_h2[(size_t)warp * GOUT + 32 + lane];
    float s = v0 * a_src[lane] + v1 * a_src[32 + lane];
    float d = v0 * a_dst[lane] + v1 * a_dst[32 + lane];
    #pragma unroll
    for (int o = 16; o; o >>= 1) {
        s += __shfl_xor_sync(0xffffffffu, s, o);
        d += __shfl_xor_sync(0xffffffffu, d, o);
    }
    if (lane == 0) {
        g_as2[warp] = s;
        g_ad2[warp] = d;
    }
}

// ---------------- layer-1 aggregation (warp per dst, no max pass) --------------
__global__ void __launch_bounds__(256) agg1_kernel(const float* __restrict__ b1) {
    int dst = (blockIdx.x * blockDim.x + threadIdx.x) >> 5;
    int lane = threadIdx.x & 31;
    if (dst >= GN) return;

    float ad[GH];
    {
        const float4* adp = reinterpret_cast<const float4*>(g_ad1 + (size_t)dst * GH);
        float4 d0 = adp[0], d1 = adp[1];
        ad[0] = d0.x; ad[1] = d0.y; ad[2] = d0.z; ad[3] = d0.w;
        ad[4] = d1.x; ad[5] = d1.y; ad[6] = d1.z; ad[7] = d1.w;
    }
    const int rs = g_rowptr[dst];
    const int re = g_rowptr[dst + 1];

    float acc[GH], den[GH];
    {   // self loop
        const float4* ap = reinterpret_cast<const float4*>(g_as1 + (size_t)dst * GH);
        float4 a0 = ap[0], a1 = ap[1];
        float av[GH] = {a0.x, a0.y, a0.z, a0.w, a1.x, a1.y, a1.z, a1.w};
        const float* hp = g_h1 + (size_t)dst * GF1;
        #pragma unroll
        for (int h = 0; h < GH; h++) {
            float w = __expf(lrelu(av[h] + ad[h]));
            den[h] = w;
            acc[h] = w * hp[h * GHID + lane];
        }
    }
    for (int e = rs; e < re; e++) {
        int src = g_srcs[e];                       // uniform load -> broadcast
        const float4* ap = reinterpret_cast<const float4*>(g_as1 + (size_t)src * GH);
        float4 a0 = ap[0], a1 = ap[1];
        float av[GH] = {a0.x, a0.y, a0.z, a0.w, a1.x, a1.y, a1.z, a1.w};
        const float* hp = g_h1 + (size_t)src * GF1;
        #pragma unroll
        for (int h = 0; h < GH; h++) {
            float w = __expf(lrelu(av[h] + ad[h]));
            den[h] += w;
            acc[h] += w * hp[h * GHID + lane];     // 128B coalesced per head
        }
    }
    #pragma unroll
    for (int h = 0; h < GH; h++) {
        float v = acc[h] / den[h] + b1[h * GHID + lane];
        g_out1[(size_t)dst * GF1 + h * GHID + lane] = fmaxf(v, 0.f);   // relu fused
    }
}

// ---------------- layer-2 aggregation + bias + log_softmax (warp per dst) ------
__global__ void __launch_bounds__(256) agg2_kernel(const float* __restrict__ b2,
                                                   float* __restrict__ out) {
    int dst = (blockIdx.x * blockDim.x + threadIdx.x) >> 5;
    int lane = threadIdx.x & 31;
    if (dst >= GN) return;

    const float ad = g_ad2[dst];
    const int rs = g_rowptr[dst];
    const int re = g_rowptr[dst + 1];

    float den, a0, a1;
    {
        float w = __expf(lrelu(g_as2[dst] + ad));
        den = w;
        a0 = w * g_h2[(size_t)dst * GOUT + lane];
        a1 = w * g_h2[(size_t)dst * GOUT + 32 + lane];
    }
    for (int e = rs; e < re; e++) {
        int src = g_srcs[e];
        float w = __expf(lrelu(g_as2[src] + ad));
        den += w;
        a0 += w * g_h2[(size_t)src * GOUT + lane];
        a1 += w * g_h2[(size_t)src * GOUT + 32 + lane];
    }
    float v0 = a0 / den + b2[lane];
    float v1 = a1 / den + b2[32 + lane];

    float m = fmaxf(v0, v1);
    #pragma unroll
    for (int o = 16; o; o >>= 1) m = fmaxf(m, __shfl_xor_sync(0xffffffffu, m, o));
    float s = __expf(v0 - m) + __expf(v1 - m);
    #pragma unroll
    for (int o = 16; o; o >>= 1) s += __shfl_xor_sync(0xffffffffu, s, o);
    float ls = __logf(s);

    out[(size_t)dst * GOUT + lane] = v0 - m - ls;
    out[(size_t)dst * GOUT + 32 + lane] = v1 - m - ls;
}

// ---------------- launch --------------------------------------------------------
extern "C" void kernel_launch(void* const* d_in, const int* in_sizes, int n_in,
                              void* d_out, int out_size) {
    const float* x      = (const float*)d_in[0];
    const int*   ei     = (const int*)d_in[1];
    const float* W1     = (const float*)d_in[2];
    const float* a_src1 = (const float*)d_in[3];
    const float* a_dst1 = (const float*)d_in[4];
    const float* b1     = (const float*)d_in[5];
    const float* W2     = (const float*)d_in[6];
    const float* a_src2 = (const float*)d_in[7];
    const float* a_dst2 = (const float*)d_in[8];
    const float* b2     = (const float*)d_in[9];
    float* out = (float*)d_out;
    const int E = in_sizes[1] / 2;

    float *h1p, *out1p, *h2p, *as1p, *ad1p;
    void* cntp;
    cudaGetSymbolAddress((void**)&h1p, g_h1);
    cudaGetSymbolAddress((void**)&out1p, g_out1);
    cudaGetSymbolAddress((void**)&h2p, g_h2);
    cudaGetSymbolAddress((void**)&as1p, g_as1);
    cudaGetSymbolAddress((void**)&ad1p, g_ad1);
    cudaGetSymbolAddress(&cntp, g_cnt);

    // CSR build
    cudaMemsetAsync(cntp, 0, GN * sizeof(int));
    hist_kernel<<<(E + 255) / 256, 256>>>(ei, E);
    scan_kernel<<<1, 1024>>>(GN);
    scatter_kernel<<<(E + 255) / 256, 256>>>(ei, E);

    // layer 1: GEMM (tf32 tensor cores) with fused alpha epilogue
    gemm_tf32_kernel<128, true>
        <<<dim3(GF1 / 128, (GN + 127) / 128), 256>>>(
            x, W1, h1p, GN, GIN, GF1, a_src1, a_dst1, as1p, ad1p);
    agg1_kernel<<<(GN + 7) / 8, 256>>>(b1);

    // layer 2
    gemm_tf32_kernel<64, false>
        <<<dim3(GOUT / 64, (GN + 127) / 128), 256>>>(
            out1p, W2, h2p, GN, GF1, GOUT, nullptr, nullptr, nullptr, nullptr);
    alpha2_kernel<<<(GN + 7) / 8, 256>>>(a_src2, a_dst2);
    agg2_kernel<<<(GN + 7) / 8, 256>>>(b2, out);
}

// round 5
// speedup vs baseline: 3.1488x; 2.0182x over previous
#include <cuda_runtime.h>
#include <cuda_bf16.h>
#include <cstdint>

#define GN 50000      // nodes
#define GE 800000     // edges (without self loops)
#define GIN 256       // in_dim
#define GH 8          // heads layer1
#define GHID 32       // hidden per head
#define GF1 256       // H*HID
#define GOUT 64       // classes
#define NB  ((GN + 255) / 256)

// ---------------- scratch (device globals) -------------------------------------
__device__ __nv_bfloat16 g_h1b[(size_t)GN * GF1];    // x @ W1, bf16
__device__ __nv_bfloat16 g_out1b[(size_t)GN * GF1];  // relu(gat1), bf16
__device__ __nv_bfloat16 g_h2b[(size_t)GN * GOUT];   // out1 @ W2, bf16
__device__ float g_as1[(size_t)GN * GH];
__device__ float g_ad1[(size_t)GN * GH];
__device__ float g_as2[GN];
__device__ float g_ad2[GN];
__device__ int   g_cnt[GN];        // histogram -> cursor
__device__ int   g_rowptr[GN + 1];
__device__ int   g_srcs[GE];       // src ids bucketed by dst
__device__ int   g_bsum[NB + 1];

__device__ __forceinline__ float lrelu(float x) { return fmaxf(x, 0.2f * x); }

__device__ __forceinline__ uint32_t pack_bf16x2(float lo, float hi) {
    uint32_t r;
    asm("cvt.rn.bf16x2.f32 %0, %1, %2;" : "=r"(r) : "f"(hi), "f"(lo));
    return r;
}
__device__ __forceinline__ float2 unpack_bf16x2(uint32_t u) {
    float2 f;
    f.x = __uint_as_float(u << 16);
    f.y = __uint_as_float(u & 0xffff0000u);
    return f;
}
__device__ __forceinline__ uint32_t smem_u32(const void* p) {
    return (uint32_t)__cvta_generic_to_shared(p);
}
__device__ __forceinline__ void ldsm_x4(uint32_t* r, uint32_t addr) {
    asm volatile("ldmatrix.sync.aligned.m8n8.x4.shared.b16 {%0,%1,%2,%3}, [%4];\n"
                 : "=r"(r[0]), "=r"(r[1]), "=r"(r[2]), "=r"(r[3]) : "r"(addr));
}
__device__ __forceinline__ void ldsm_x4_t(uint32_t* r, uint32_t addr) {
    asm volatile("ldmatrix.sync.aligned.m8n8.x4.trans.shared.b16 {%0,%1,%2,%3}, [%4];\n"
                 : "=r"(r[0]), "=r"(r[1]), "=r"(r[2]), "=r"(r[3]) : "r"(addr));
}
__device__ __forceinline__ void mma_bf16(float* c, const uint32_t* a, uint32_t b0, uint32_t b1) {
    asm volatile(
        "mma.sync.aligned.m16n8k16.row.col.f32.bf16.bf16.f32 "
        "{%0,%1,%2,%3},{%4,%5,%6,%7},{%8,%9},{%0,%1,%2,%3};\n"
        : "+f"(c[0]), "+f"(c[1]), "+f"(c[2]), "+f"(c[3])
        : "r"(a[0]), "r"(a[1]), "r"(a[2]), "r"(a[3]), "r"(b0), "r"(b1));
}

// ---------------- CSR build ----------------------------------------------------
__global__ void hist_kernel(const int* __restrict__ ei, int E) {
    int e = blockIdx.x * blockDim.x + threadIdx.x;
    if (e < E) atomicAdd(&g_cnt[ei[E + e]], 1);
}

__global__ void block_sum_kernel() {
    __shared__ int ws[8];
    int i = blockIdx.x * 256 + threadIdx.x;
    int v = (i < GN) ? g_cnt[i] : 0;
    int s = v;
    #pragma unroll
    for (int o = 16; o; o >>= 1) s += __shfl_xor_sync(0xffffffffu, s, o);
    if ((threadIdx.x & 31) == 0) ws[threadIdx.x >> 5] = s;
    __syncthreads();
    if (threadIdx.x < 8) {
        int t = ws[threadIdx.x];
        #pragma unroll
        for (int o = 4; o; o >>= 1) t += __shfl_xor_sync(0xffu, t, o);
        if (threadIdx.x == 0) g_bsum[blockIdx.x] = t;
    }
}

__global__ void scan_sums_kernel() {   // one block, 256 threads; NB <= 256
    __shared__ int ws[8];
    int lane = threadIdx.x & 31, wid = threadIdx.x >> 5;
    int v = (threadIdx.x < NB) ? g_bsum[threadIdx.x] : 0;
    int s = v;
    #pragma unroll
    for (int o = 1; o < 32; o <<= 1) {
        int t = __shfl_up_sync(0xffffffffu, s, o);
        if (lane >= o) s += t;
    }
    if (lane == 31) ws[wid] = s;
    __syncthreads();
    if (wid == 0 && lane < 8) {
        int t = ws[lane];
        #pragma unroll
        for (int o = 1; o < 8; o <<= 1) {
            int u = __shfl_up_sync(0xffu, t, o);
            if (lane >= o) t += u;
        }
        ws[lane] = t;
    }
    __syncthreads();
    int incl = s + (wid ? ws[wid - 1] : 0);
    if (threadIdx.x < NB) g_bsum[threadIdx.x] = incl - v;   // exclusive
}

__global__ void scan_apply_kernel() {
    __shared__ int ws[8];
    int lane = threadIdx.x & 31, wid = threadIdx.x >> 5;
    int i = blockIdx.x * 256 + threadIdx.x;
    int v = (i < GN) ? g_cnt[i] : 0;
    int s = v;
    #pragma unroll
    for (int o = 1; o < 32; o <<= 1) {
        int t = __shfl_up_sync(0xffffffffu, s, o);
        if (lane >= o) s += t;
    }
    if (lane == 31) ws[wid] = s;
    __syncthreads();
    if (wid == 0 && lane < 8) {
        int t = ws[lane];
        #pragma unroll
        for (int o = 1; o < 8; o <<= 1) {
            int u = __shfl_up_sync(0xffu, t, o);
            if (lane >= o) t += u;
        }
        ws[lane] = t;
    }
    __syncthreads();
    int incl = s + (wid ? ws[wid - 1] : 0) + g_bsum[blockIdx.x];
    if (i < GN) {
        g_rowptr[i + 1] = incl;
        g_cnt[i] = incl - v;   // exclusive -> scatter cursor
    }
    if (i == 0) g_rowptr[0] = 0;
}

__global__ void scatter_kernel(const int* __restrict__ ei, int E) {
    int e = blockIdx.x * blockDim.x + threadIdx.x;
    if (e < E) {
        int dst = ei[E + e];
        int pos = atomicAdd(&g_cnt[dst], 1);
        g_srcs[pos] = ei[e];
    }
}

// ---------------- BF16 tensor-core GEMM ----------------------------------------
// BM=128, BK=32, 256 threads, warps 4(M) x 2(N). C stored bf16.
// A_BF16: input A is bf16 (else fp32, converted while staging).
// FUSE: compute alpha_src/alpha_dst per (row, head of 32 cols) from fp32 acc.
template <int BN, bool A_BF16, bool FUSE>
__global__ void __launch_bounds__(256) gemm_bf16_kernel(
    const void* __restrict__ Av, const float* __restrict__ B,
    __nv_bfloat16* __restrict__ C, int M, int K, int Nc,
    const float* __restrict__ a_src, const float* __restrict__ a_dst,
    float* __restrict__ g_as, float* __restrict__ g_ad) {
    constexpr int NT = BN / 16;       // n8-tiles per warp
    constexpr int NP = NT / 2;        // ldmatrix.x4 groups per warp
    constexpr int SBS = BN + 8;       // sB row stride (bf16)
    __shared__ __nv_bfloat16 sA[128 * 40];
    __shared__ __nv_bfloat16 sB[32 * SBS];

    const int tid = threadIdx.x, lane = tid & 31, wid = tid >> 5;
    const int warpM = wid & 3, warpN = wid >> 2;
    const int rowBase = blockIdx.y * 128;
    const int colBase = blockIdx.x * BN;
    const int wcb = colBase + warpN * (BN / 2);

    const uint32_t sAu = smem_u32(sA), sBu = smem_u32(sB);
    const int aRow = warpM * 32 + (lane & 7) + ((lane >> 3) & 1) * 8;
    const uint32_t aAddr = sAu + (uint32_t)(aRow * 40 + ((lane >> 4) * 8)) * 2;
    const int bRow = (lane & 7) + ((lane >> 3) & 1) * 8;
    const uint32_t bAddr = sBu + (uint32_t)(bRow * SBS + warpN * (BN / 2) + (lane >> 4) * 8) * 2;

    float c[2][NT][4];
    #pragma unroll
    for (int i = 0; i < 2; i++)
        #pragma unroll
        for (int j = 0; j < NT; j++)
            #pragma unroll
            for (int q = 0; q < 4; q++) c[i][j][q] = 0.f;

    for (int k0 = 0; k0 < K; k0 += 32) {
        if (k0) __syncthreads();
        // ---- stage A (128 x 32)
        if (A_BF16) {
            const __nv_bfloat16* Ab = (const __nv_bfloat16*)Av;
            #pragma unroll
            for (int i = 0; i < 2; i++) {
                int f = tid + i * 256;          // 512 uint4
                int r = f >> 2, c8 = (f & 3) * 8;
                uint4 v = make_uint4(0, 0, 0, 0);
                if (rowBase + r < M)
                    v = *reinterpret_cast<const uint4*>(Ab + (size_t)(rowBase + r) * K + k0 + c8);
                *reinterpret_cast<uint4*>(&sA[r * 40 + c8]) = v;
            }
        } else {
            const float* Af = (const float*)Av;
            #pragma unroll
            for (int i = 0; i < 4; i++) {
                int f = tid + i * 256;          // 1024 float4
                int r = f >> 3, c4 = (f & 7) * 4;
                float4 v = make_float4(0.f, 0.f, 0.f, 0.f);
                if (rowBase + r < M)
                    v = *reinterpret_cast<const float4*>(Af + (size_t)(rowBase + r) * K + k0 + c4);
                uint2 p = make_uint2(pack_bf16x2(v.x, v.y), pack_bf16x2(v.z, v.w));
                *reinterpret_cast<uint2*>(&sA[r * 40 + c4]) = p;
            }
        }
        // ---- stage B (32 x BN), fp32 -> bf16
        constexpr int BL = 32 * BN / 1024;
        #pragma unroll
        for (int i = 0; i < BL; i++) {
            int f = tid + i * 256;
            int krow = f / (BN / 4), c4 = (f % (BN / 4)) * 4;
            float4 v = *reinterpret_cast<const float4*>(B + (size_t)(k0 + krow) * Nc + colBase + c4);
            uint2 p = make_uint2(pack_bf16x2(v.x, v.y), pack_bf16x2(v.z, v.w));
            *reinterpret_cast<uint2*>(&sB[krow * SBS + c4]) = p;
        }
        __syncthreads();
        // ---- compute
        #pragma unroll
        for (int ks = 0; ks < 2; ks++) {
            uint32_t a[2][4];
            #pragma unroll
            for (int mt = 0; mt < 2; mt++)
                ldsm_x4(a[mt], aAddr + (uint32_t)(mt * 16 * 40 + ks * 16) * 2);
            uint32_t b[NP][4];
            #pragma unroll
            for (int np = 0; np < NP; np++)
                ldsm_x4_t(b[np], bAddr + (uint32_t)(ks * 16 * SBS + np * 16) * 2);
            #pragma unroll
            for (int mt = 0; mt < 2; mt++)
                #pragma unroll
                for (int nt = 0; nt < NT; nt++) {
                    int np = nt >> 1;
                    mma_bf16(c[mt][nt], a[mt], b[np][(nt & 1) * 2], b[np][(nt & 1) * 2 + 1]);
                }
        }
    }

    // ---- epilogue: store C as bf16
    #pragma unroll
    for (int mt = 0; mt < 2; mt++)
        #pragma unroll
        for (int half = 0; half < 2; half++) {
            int row = rowBase + warpM * 32 + mt * 16 + (lane >> 2) + half * 8;
            if (row < M) {
                #pragma unroll
                for (int nt = 0; nt < NT; nt++) {
                    int col = wcb + nt * 8 + (lane & 3) * 2;
                    uint32_t u = pack_bf16x2(c[mt][nt][half * 2], c[mt][nt][half * 2 + 1]);
                    *reinterpret_cast<uint32_t*>(C + (size_t)row * Nc + col) = u;
                }
            }
        }

    if (FUSE) {
        float asc[NT * 2], adc[NT * 2];
        #pragma unroll
        for (int nt = 0; nt < NT; nt++)
            #pragma unroll
            for (int j = 0; j < 2; j++) {
                int col = wcb + nt * 8 + (lane & 3) * 2 + j;
                asc[nt * 2 + j] = a_src[col];
                adc[nt * 2 + j] = a_dst[col];
            }
        int headBase = wcb >> 5;
        #pragma unroll
        for (int mt = 0; mt < 2; mt++)
            #pragma unroll
            for (int half = 0; half < 2; half++) {
                int row = rowBase + warpM * 32 + mt * 16 + (lane >> 2) + half * 8;
                float ss0 = 0.f, ss1 = 0.f, sd0 = 0.f, sd1 = 0.f;
                #pragma unroll
                for (int nt = 0; nt < NT; nt++)
                    #pragma unroll
                    for (int j = 0; j < 2; j++) {
                        float v = c[mt][nt][half * 2 + j];
                        if (nt < NT / 2) { ss0 += v * asc[nt * 2 + j]; sd0 += v * adc[nt * 2 + j]; }
                        else             { ss1 += v * asc[nt * 2 + j]; sd1 += v * adc[nt * 2 + j]; }
                    }
                #pragma unroll
                for (int o = 1; o <= 2; o <<= 1) {
                    ss0 += __shfl_xor_sync(0xffffffffu, ss0, o);
                    ss1 += __shfl_xor_sync(0xffffffffu, ss1, o);
                    sd0 += __shfl_xor_sync(0xffffffffu, sd0, o);
                    sd1 += __shfl_xor_sync(0xffffffffu, sd1, o);
                }
                if ((lane & 3) == 0 && row < M) {
                    g_as[(size_t)row * GH + headBase]     = ss0;
                    g_as[(size_t)row * GH + headBase + 1] = ss1;
                    g_ad[(size_t)row * GH + headBase]     = sd0;
                    g_ad[(size_t)row * GH + headBase + 1] = sd1;
                }
            }
    }
}

// ---------------- alpha2 (from bf16 h2) ----------------------------------------
__global__ void alpha2_kernel(const float* __restrict__ a_src, const float* __restrict__ a_dst) {
    int warp = (blockIdx.x * blockDim.x + threadIdx.x) >> 5;
    int lane = threadIdx.x & 31;
    if (warp >= GN) return;
    uint32_t u = *reinterpret_cast<const uint32_t*>(g_h2b + (size_t)warp * GOUT + 2 * lane);
    float2 v = unpack_bf16x2(u);
    float2 as = *reinterpret_cast<const float2*>(a_src + 2 * lane);
    float2 adv = *reinterpret_cast<const float2*>(a_dst + 2 * lane);
    float s = v.x * as.x + v.y * as.y;
    float d = v.x * adv.x + v.y * adv.y;
    #pragma unroll
    for (int o = 16; o; o >>= 1) {
        s += __shfl_xor_sync(0xffffffffu, s, o);
        d += __shfl_xor_sync(0xffffffffu, d, o);
    }
    if (lane == 0) {
        g_as2[warp] = s;
        g_ad2[warp] = d;
    }
}

// ---------------- layer-1 aggregation (warp per dst) ---------------------------
// lane l covers cols [8l, 8l+8) -> single head (l>>2). One LDG.128 per edge.
__global__ void __launch_bounds__(256) agg1_kernel(const float* __restrict__ b1) {
    int dst = (blockIdx.x * blockDim.x + threadIdx.x) >> 5;
    int lane = threadIdx.x & 31;
    if (dst >= GN) return;
    const int head = lane >> 2;

    const float ad = g_ad1[(size_t)dst * GH + head];
    const int rs = g_rowptr[dst];
    const int re = g_rowptr[dst + 1];

    float acc[8];
    float den;
    {   // self loop
        float w = __expf(lrelu(g_as1[(size_t)dst * GH + head] + ad));
        den = w;
        uint4 u = *reinterpret_cast<const uint4*>(g_h1b + (size_t)dst * GF1 + lane * 8);
        float2 f0 = unpack_bf16x2(u.x), f1 = unpack_bf16x2(u.y);
        float2 f2 = unpack_bf16x2(u.z), f3 = unpack_bf16x2(u.w);
        acc[0] = w * f0.x; acc[1] = w * f0.y; acc[2] = w * f1.x; acc[3] = w * f1.y;
        acc[4] = w * f2.x; acc[5] = w * f2.y; acc[6] = w * f3.x; acc[7] = w * f3.y;
    }
    int src = (rs < re) ? g_srcs[rs] : 0;
    for (int e = rs; e < re; e++) {
        int cur = src;
        if (e + 1 < re) src = g_srcs[e + 1];
        float w = __expf(lrelu(g_as1[(size_t)cur * GH + head] + ad));
        den += w;
        uint4 u = *reinterpret_cast<const uint4*>(g_h1b + (size_t)cur * GF1 + lane * 8);
        float2 f0 = unpack_bf16x2(u.x), f1 = unpack_bf16x2(u.y);
        float2 f2 = unpack_bf16x2(u.z), f3 = unpack_bf16x2(u.w);
        acc[0] += w * f0.x; acc[1] += w * f0.y; acc[2] += w * f1.x; acc[3] += w * f1.y;
        acc[4] += w * f2.x; acc[5] += w * f2.y; acc[6] += w * f3.x; acc[7] += w * f3.y;
    }
    float inv = 1.f / den;
    float4 bb0 = *reinterpret_cast<const float4*>(b1 + lane * 8);
    float4 bb1 = *reinterpret_cast<const float4*>(b1 + lane * 8 + 4);
    float bv[8] = {bb0.x, bb0.y, bb0.z, bb0.w, bb1.x, bb1.y, bb1.z, bb1.w};
    uint4 st;
    uint32_t* stp = reinterpret_cast<uint32_t*>(&st);
    #pragma unroll
    for (int p = 0; p < 4; p++) {
        float v0 = fmaxf(acc[2 * p] * inv + bv[2 * p], 0.f);
        float v1 = fmaxf(acc[2 * p + 1] * inv + bv[2 * p + 1], 0.f);
        stp[p] = pack_bf16x2(v0, v1);
    }
    *reinterpret_cast<uint4*>(g_out1b + (size_t)dst * GF1 + lane * 8) = st;
}

// ---------------- layer-2 aggregation + bias + log_softmax ---------------------
__global__ void __launch_bounds__(256) agg2_kernel(const float* __restrict__ b2,
                                                   float* __restrict__ out) {
    int dst = (blockIdx.x * blockDim.x + threadIdx.x) >> 5;
    int lane = threadIdx.x & 31;
    if (dst >= GN) return;

    const float ad = g_ad2[dst];
    const int rs = g_rowptr[dst];
    const int re = g_rowptr[dst + 1];

    float den, a0, a1;
    {
        float w = __expf(lrelu(g_as2[dst] + ad));
        den = w;
        uint32_t u = *reinterpret_cast<const uint32_t*>(g_h2b + (size_t)dst * GOUT + 2 * lane);
        float2 f = unpack_bf16x2(u);
        a0 = w * f.x;
        a1 = w * f.y;
    }
    int src = (rs < re) ? g_srcs[rs] : 0;
    for (int e = rs; e < re; e++) {
        int cur = src;
        if (e + 1 < re) src = g_srcs[e + 1];
        float w = __expf(lrelu(g_as2[cur] + ad));
        den += w;
        uint32_t u = *reinterpret_cast<const uint32_t*>(g_h2b + (size_t)cur * GOUT + 2 * lane);
        float2 f = unpack_bf16x2(u);
        a0 += w * f.x;
        a1 += w * f.y;
    }
    float2 bb = *reinterpret_cast<const float2*>(b2 + 2 * lane);
    float inv = 1.f / den;
    float v0 = a0 * inv + bb.x;
    float v1 = a1 * inv + bb.y;

    float m = fmaxf(v0, v1);
    #pragma unroll
    for (int o = 16; o; o >>= 1) m = fmaxf(m, __shfl_xor_sync(0xffffffffu, m, o));
    float s = __expf(v0 - m) + __expf(v1 - m);
    #pragma unroll
    for (int o = 16; o; o >>= 1) s += __shfl_xor_sync(0xffffffffu, s, o);
    float ls = __logf(s) + m;

    float2 st = make_float2(v0 - ls, v1 - ls);
    *reinterpret_cast<float2*>(out + (size_t)dst * GOUT + 2 * lane) = st;
}

// ---------------- launch --------------------------------------------------------
extern "C" void kernel_launch(void* const* d_in, const int* in_sizes, int n_in,
                              void* d_out, int out_size) {
    const float* x      = (const float*)d_in[0];
    const int*   ei     = (const int*)d_in[1];
    const float* W1     = (const float*)d_in[2];
    const float* a_src1 = (const float*)d_in[3];
    const float* a_dst1 = (const float*)d_in[4];
    const float* b1     = (const float*)d_in[5];
    const float* W2     = (const float*)d_in[6];
    const float* a_src2 = (const float*)d_in[7];
    const float* a_dst2 = (const float*)d_in[8];
    const float* b2     = (const float*)d_in[9];
    float* out = (float*)d_out;
    const int E = in_sizes[1] / 2;

    __nv_bfloat16 *h1p, *out1p, *h2p;
    float *as1p, *ad1p;
    void* cntp;
    cudaGetSymbolAddress((void**)&h1p, g_h1b);
    cudaGetSymbolAddress((void**)&out1p, g_out1b);
    cudaGetSymbolAddress((void**)&h2p, g_h2b);
    cudaGetSymbolAddress((void**)&as1p, g_as1);
    cudaGetSymbolAddress((void**)&ad1p, g_ad1);
    cudaGetSymbolAddress(&cntp, g_cnt);

    // CSR build
    cudaMemsetAsync(cntp, 0, GN * sizeof(int));
    hist_kernel<<<(E + 255) / 256, 256>>>(ei, E);
    block_sum_kernel<<<NB, 256>>>();
    scan_sums_kernel<<<1, 256>>>();
    scan_apply_kernel<<<NB, 256>>>();
    scatter_kernel<<<(E + 255) / 256, 256>>>(ei, E);

    // layer 1: bf16 tensor GEMM with fused alpha epilogue
    gemm_bf16_kernel<128, false, true>
        <<<dim3(GF1 / 128, (GN + 127) / 128), 256>>>(
            x, W1, h1p, GN, GIN, GF1, a_src1, a_dst1, as1p, ad1p);
    agg1_kernel<<<(GN + 7) / 8, 256>>>(b1);

    // layer 2
    gemm_bf16_kernel<64, true, false>
        <<<dim3(GOUT / 64, (GN + 127) / 128), 256>>>(
            out1p, W2, h2p, GN, GF1, GOUT, nullptr, nullptr, nullptr, nullptr);
    alpha2_kernel<<<(GN + 7) / 8, 256>>>(a_src2, a_dst2);
    agg2_kernel<<<(GN + 7) / 8, 256>>>(b2, out);
}

// round 6
// speedup vs baseline: 3.3763x; 1.0723x over previous
#include <cuda_runtime.h>
#include <cuda_bf16.h>
#include <cstdint>

#define GN 50000      // nodes
#define GE 800000     // edges (without self loops)
#define GIN 256       // in_dim
#define GH 8          // heads layer1
#define GHID 32       // hidden per head
#define GF1 256       // H*HID
#define GOUT 64       // classes
#define NB  ((GN + 255) / 256)

// ---------------- scratch (device globals) -------------------------------------
__device__ __nv_bfloat16 g_xb[(size_t)GN * GIN];     // x in bf16
__device__ __nv_bfloat16 g_w1b[GIN * GF1];           // W1 bf16
__device__ __nv_bfloat16 g_w2b[GF1 * GOUT];          // W2 bf16
__device__ __nv_bfloat16 g_h1b[(size_t)GN * GF1];    // x @ W1, bf16
__device__ __nv_bfloat16 g_out1b[(size_t)GN * GF1];  // relu(gat1), bf16
__device__ __nv_bfloat16 g_h2b[(size_t)GN * GOUT];   // out1 @ W2, bf16
__device__ float g_as1[(size_t)GN * GH];
__device__ float g_ad1[(size_t)GN * GH];
__device__ float g_as2[GN];
__device__ float g_ad2[GN];
__device__ int   g_cnt[GN];        // histogram -> cursor
__device__ int   g_rowptr[GN + 1];
__device__ int   g_srcs[GE];       // src ids bucketed by dst
__device__ int   g_bsum[NB + 1];

__device__ __forceinline__ float lrelu(float x) { return fmaxf(x, 0.2f * x); }

__device__ __forceinline__ uint32_t pack_bf16x2(float lo, float hi) {
    uint32_t r;
    asm("cvt.rn.bf16x2.f32 %0, %1, %2;" : "=r"(r) : "f"(hi), "f"(lo));
    return r;
}
__device__ __forceinline__ float2 unpack_bf16x2(uint32_t u) {
    float2 f;
    f.x = __uint_as_float(u << 16);
    f.y = __uint_as_float(u & 0xffff0000u);
    return f;
}
__device__ __forceinline__ uint32_t smem_u32(const void* p) {
    return (uint32_t)__cvta_generic_to_shared(p);
}
__device__ __forceinline__ void cp_async16(uint32_t dst, const void* src, bool pred) {
    int sz = pred ? 16 : 0;
    asm volatile("cp.async.cg.shared.global [%0], [%1], 16, %2;\n"
                 :: "r"(dst), "l"(src), "r"(sz));
}
__device__ __forceinline__ void cp_commit() {
    asm volatile("cp.async.commit_group;\n");
}
__device__ __forceinline__ void ldsm_x4(uint32_t* r, uint32_t addr) {
    asm volatile("ldmatrix.sync.aligned.m8n8.x4.shared.b16 {%0,%1,%2,%3}, [%4];\n"
                 : "=r"(r[0]), "=r"(r[1]), "=r"(r[2]), "=r"(r[3]) : "r"(addr));
}
__device__ __forceinline__ void ldsm_x4_t(uint32_t* r, uint32_t addr) {
    asm volatile("ldmatrix.sync.aligned.m8n8.x4.trans.shared.b16 {%0,%1,%2,%3}, [%4];\n"
                 : "=r"(r[0]), "=r"(r[1]), "=r"(r[2]), "=r"(r[3]) : "r"(addr));
}
__device__ __forceinline__ void mma_bf16(float* c, const uint32_t* a, uint32_t b0, uint32_t b1) {
    asm volatile(
        "mma.sync.aligned.m16n8k16.row.col.f32.bf16.bf16.f32 "
        "{%0,%1,%2,%3},{%4,%5,%6,%7},{%8,%9},{%0,%1,%2,%3};\n"
        : "+f"(c[0]), "+f"(c[1]), "+f"(c[2]), "+f"(c[3])
        : "r"(a[0]), "r"(a[1]), "r"(a[2]), "r"(a[3]), "r"(b0), "r"(b1));
}

// ---------------- fp32 -> bf16 conversion (x, W1, W2) --------------------------
__global__ void convert_kernel(const float* __restrict__ x,
                               const float* __restrict__ W1,
                               const float* __restrict__ W2) {
    int i = blockIdx.x * blockDim.x + threadIdx.x;
    int stride = gridDim.x * blockDim.x;
    const int TX = GN * GIN / 8;
    for (int t = i; t < TX; t += stride) {
        float4 v0 = reinterpret_cast<const float4*>(x)[t * 2];
        float4 v1 = reinterpret_cast<const float4*>(x)[t * 2 + 1];
        uint4 u = make_uint4(pack_bf16x2(v0.x, v0.y), pack_bf16x2(v0.z, v0.w),
                             pack_bf16x2(v1.x, v1.y), pack_bf16x2(v1.z, v1.w));
        reinterpret_cast<uint4*>(g_xb)[t] = u;
    }
    const int T1 = GIN * GF1 / 8;
    for (int t = i; t < T1; t += stride) {
        float4 v0 = reinterpret_cast<const float4*>(W1)[t * 2];
        float4 v1 = reinterpret_cast<const float4*>(W1)[t * 2 + 1];
        uint4 u = make_uint4(pack_bf16x2(v0.x, v0.y), pack_bf16x2(v0.z, v0.w),
                             pack_bf16x2(v1.x, v1.y), pack_bf16x2(v1.z, v1.w));
        reinterpret_cast<uint4*>(g_w1b)[t] = u;
    }
    const int T2 = GF1 * GOUT / 8;
    for (int t = i; t < T2; t += stride) {
        float4 v0 = reinterpret_cast<const float4*>(W2)[t * 2];
        float4 v1 = reinterpret_cast<const float4*>(W2)[t * 2 + 1];
        uint4 u = make_uint4(pack_bf16x2(v0.x, v0.y), pack_bf16x2(v0.z, v0.w),
                             pack_bf16x2(v1.x, v1.y), pack_bf16x2(v1.z, v1.w));
        reinterpret_cast<uint4*>(g_w2b)[t] = u;
    }
}

// ---------------- CSR build ----------------------------------------------------
__global__ void hist_kernel(const int* __restrict__ ei, int E) {
    int i = blockIdx.x * blockDim.x + threadIdx.x;
    int n4 = E >> 2;
    if (i < n4) {
        int4 d = reinterpret_cast<const int4*>(ei + E)[i];
        atomicAdd(&g_cnt[d.x], 1);
        atomicAdd(&g_cnt[d.y], 1);
        atomicAdd(&g_cnt[d.z], 1);
        atomicAdd(&g_cnt[d.w], 1);
    } else if (i < n4 + (E & 3)) {
        atomicAdd(&g_cnt[ei[E + n4 * 4 + (i - n4)]], 1);
    }
}

__global__ void block_sum_kernel() {
    __shared__ int ws[8];
    int i = blockIdx.x * 256 + threadIdx.x;
    int v = (i < GN) ? g_cnt[i] : 0;
    int s = v;
    #pragma unroll
    for (int o = 16; o; o >>= 1) s += __shfl_xor_sync(0xffffffffu, s, o);
    if ((threadIdx.x & 31) == 0) ws[threadIdx.x >> 5] = s;
    __syncthreads();
    if (threadIdx.x < 8) {
        int t = ws[threadIdx.x];
        #pragma unroll
        for (int o = 4; o; o >>= 1) t += __shfl_xor_sync(0xffu, t, o);
        if (threadIdx.x == 0) g_bsum[blockIdx.x] = t;
    }
}

__global__ void scan_apply_kernel() {
    __shared__ int ws[8];
    __shared__ int s_off;
    int tid = threadIdx.x, lane = tid & 31, wid = tid >> 5;

    // block offset = sum of g_bsum[j] for j < blockIdx.x
    int a = 0;
    for (int j = tid; j < blockIdx.x; j += 256) a += g_bsum[j];
    #pragma unroll
    for (int o = 16; o; o >>= 1) a += __shfl_xor_sync(0xffffffffu, a, o);
    if (lane == 0) ws[wid] = a;
    __syncthreads();
    if (tid == 0) {
        int t = 0;
        #pragma unroll
        for (int k = 0; k < 8; k++) t += ws[k];
        s_off = t;
    }
    __syncthreads();

    int i = blockIdx.x * 256 + tid;
    int v = (i < GN) ? g_cnt[i] : 0;
    int s = v;
    #pragma unroll
    for (int o = 1; o < 32; o <<= 1) {
        int t = __shfl_up_sync(0xffffffffu, s, o);
        if (lane >= o) s += t;
    }
    if (lane == 31) ws[wid] = s;
    __syncthreads();
    if (wid == 0 && lane < 8) {
        int t = ws[lane];
        #pragma unroll
        for (int o = 1; o < 8; o <<= 1) {
            int u = __shfl_up_sync(0xffu, t, o);
            if (lane >= o) t += u;
        }
        ws[lane] = t;
    }
    __syncthreads();
    int incl = s + (wid ? ws[wid - 1] : 0) + s_off;
    if (i < GN) {
        g_rowptr[i + 1] = incl;
        g_cnt[i] = incl - v;   // exclusive -> scatter cursor
    }
    if (i == 0) g_rowptr[0] = 0;
}

__global__ void scatter_kernel(const int* __restrict__ ei, int E) {
    int i = blockIdx.x * blockDim.x + threadIdx.x;
    int n4 = E >> 2;
    if (i < n4) {
        int4 sv = reinterpret_cast<const int4*>(ei)[i];
        int4 dv = reinterpret_cast<const int4*>(ei + E)[i];
        g_srcs[atomicAdd(&g_cnt[dv.x], 1)] = sv.x;
        g_srcs[atomicAdd(&g_cnt[dv.y], 1)] = sv.y;
        g_srcs[atomicAdd(&g_cnt[dv.z], 1)] = sv.z;
        g_srcs[atomicAdd(&g_cnt[dv.w], 1)] = sv.w;
    } else if (i < n4 + (E & 3)) {
        int e = n4 * 4 + (i - n4);
        g_srcs[atomicAdd(&g_cnt[ei[E + e]], 1)] = ei[e];
    }
}

// ---------------- BF16 tensor GEMM, cp.async double-buffered -------------------
// BM=128, BK=32, 256 threads, warps 4(M) x 2(N). A,B,C all bf16.
// FUSE1: per-(row, 32-col head) alpha epilogue (layer1).
// FUSE2: full-row alpha epilogue with cross-warp smem reduction (layer2).
template <int BN, bool FUSE1, bool FUSE2>
__global__ void __launch_bounds__(256) gemm_async_kernel(
    const __nv_bfloat16* __restrict__ A, const __nv_bfloat16* __restrict__ B,
    __nv_bfloat16* __restrict__ C, int M, int K, int Nc,
    const float* __restrict__ a_src, const float* __restrict__ a_dst,
    float* __restrict__ g_as, float* __restrict__ g_ad) {
    constexpr int NT = BN / 16;       // n8-tiles per warp
    constexpr int NP = NT / 2;        // ldmatrix.x4 groups per warp
    constexpr int SBS = BN + 8;       // sB row stride (bf16)
    constexpr int A_ELEM = 128 * 40;
    constexpr int B_ELEM = 32 * SBS;
    __shared__ __align__(16) __nv_bfloat16 sA[2][A_ELEM];
    __shared__ __align__(16) __nv_bfloat16 sB[2][B_ELEM];

    const int tid = threadIdx.x, lane = tid & 31, wid = tid >> 5;
    const int warpM = wid & 3, warpN = wid >> 2;
    const int rowBase = blockIdx.y * 128;
    const int colBase = blockIdx.x * BN;
    const int wcb = colBase + warpN * (BN / 2);

    const uint32_t sAu = smem_u32(&sA[0][0]), sBu = smem_u32(&sB[0][0]);
    const int aRow = warpM * 32 + (lane & 7) + ((lane >> 3) & 1) * 8;
    const uint32_t aAddr = sAu + (uint32_t)(aRow * 40 + ((lane >> 4) * 8)) * 2;
    const int bRow = (lane & 7) + ((lane >> 3) & 1) * 8;
    const uint32_t bAddr = sBu + (uint32_t)(bRow * SBS + warpN * (BN / 2) + (lane >> 4) * 8) * 2;

    auto stageA = [&](int buf, int k0) {
        #pragma unroll
        for (int i2 = 0; i2 < 2; i2++) {
            int f = tid + i2 * 256;
            int r = f >> 2, c8 = (f & 3) * 8;
            int row = rowBase + r;
            uint32_t dst = sAu + (uint32_t)(buf * A_ELEM + r * 40 + c8) * 2;
            cp_async16(dst, A + (size_t)row * K + k0 + c8, row < M);
        }
    };
    auto stageB = [&](int buf, int k0) {
        #pragma unroll
        for (int i2 = 0; i2 < BN / 64; i2++) {
            int f = tid + i2 * 256;
            int krow = f / (BN / 8), c8 = (f % (BN / 8)) * 8;
            uint32_t dst = sBu + (uint32_t)(buf * B_ELEM + krow * SBS + c8) * 2;
            cp_async16(dst, B + (size_t)(k0 + krow) * Nc + colBase + c8, true);
        }
    };

    float c[2][NT][4];
    #pragma unroll
    for (int i = 0; i < 2; i++)
        #pragma unroll
        for (int j = 0; j < NT; j++)
            #pragma unroll
            for (int q = 0; q < 4; q++) c[i][j][q] = 0.f;

    const int S = K / 32;
    stageA(0, 0);
    stageB(0, 0);
    cp_commit();

    for (int s = 0; s < S; s++) {
        const int buf = s & 1;
        if (s + 1 < S) {
            stageA(buf ^ 1, (s + 1) * 32);
            stageB(buf ^ 1, (s + 1) * 32);
            cp_commit();
            asm volatile("cp.async.wait_group 1;\n");
        } else {
            asm volatile("cp.async.wait_group 0;\n");
        }
        __syncthreads();
        const uint32_t aB = aAddr + buf * A_ELEM * 2;
        const uint32_t bB = bAddr + buf * B_ELEM * 2;
        #pragma unroll
        for (int ks = 0; ks < 2; ks++) {
            uint32_t a[2][4];
            #pragma unroll
            for (int mt = 0; mt < 2; mt++)
                ldsm_x4(a[mt], aB + (uint32_t)(mt * 16 * 40 + ks * 16) * 2);
            uint32_t b[NP][4];
            #pragma unroll
            for (int np = 0; np < NP; np++)
                ldsm_x4_t(b[np], bB + (uint32_t)(ks * 16 * SBS + np * 16) * 2);
            #pragma unroll
            for (int mt = 0; mt < 2; mt++)
                #pragma unroll
                for (int nt = 0; nt < NT; nt++) {
                    int np = nt >> 1;
                    mma_bf16(c[mt][nt], a[mt], b[np][(nt & 1) * 2], b[np][(nt & 1) * 2 + 1]);
                }
        }
        __syncthreads();
    }

    // ---- epilogue: store C as bf16
    #pragma unroll
    for (int mt = 0; mt < 2; mt++)
        #pragma unroll
        for (int half = 0; half < 2; half++) {
            int row = rowBase + warpM * 32 + mt * 16 + (lane >> 2) + half * 8;
            if (row < M) {
                #pragma unroll
                for (int nt = 0; nt < NT; nt++) {
                    int col = wcb + nt * 8 + (lane & 3) * 2;
                    uint32_t u = pack_bf16x2(c[mt][nt][half * 2], c[mt][nt][half * 2 + 1]);
                    *reinterpret_cast<uint32_t*>(C + (size_t)row * Nc + col) = u;
                }
            }
        }

    if (FUSE1) {
        // per-warp slice = 64 cols = 2 heads of 32
        float asc[NT * 2], adc[NT * 2];
        #pragma unroll
        for (int nt = 0; nt < NT; nt++)
            #pragma unroll
            for (int j = 0; j < 2; j++) {
                int col = wcb + nt * 8 + (lane & 3) * 2 + j;
                asc[nt * 2 + j] = a_src[col];
                adc[nt * 2 + j] = a_dst[col];
            }
        int headBase = wcb >> 5;
        #pragma unroll
        for (int mt = 0; mt < 2; mt++)
            #pragma unroll
            for (int half = 0; half < 2; half++) {
                int row = rowBase + warpM * 32 + mt * 16 + (lane >> 2) + half * 8;
                float ss0 = 0.f, ss1 = 0.f, sd0 = 0.f, sd1 = 0.f;
                #pragma unroll
                for (int nt = 0; nt < NT; nt++)
                    #pragma unroll
                    for (int j = 0; j < 2; j++) {
                        float v = c[mt][nt][half * 2 + j];
                        if (nt < NT / 2) { ss0 += v * asc[nt * 2 + j]; sd0 += v * adc[nt * 2 + j]; }
                        else             { ss1 += v * asc[nt * 2 + j]; sd1 += v * adc[nt * 2 + j]; }
                    }
                #pragma unroll
                for (int o = 1; o <= 2; o <<= 1) {
                    ss0 += __shfl_xor_sync(0xffffffffu, ss0, o);
                    ss1 += __shfl_xor_sync(0xffffffffu, ss1, o);
                    sd0 += __shfl_xor_sync(0xffffffffu, sd0, o);
                    sd1 += __shfl_xor_sync(0xffffffffu, sd1, o);
                }
                if ((lane & 3) == 0 && row < M) {
                    g_as[(size_t)row * GH + headBase]     = ss0;
                    g_as[(size_t)row * GH + headBase + 1] = ss1;
                    g_ad[(size_t)row * GH + headBase]     = sd0;
                    g_ad[(size_t)row * GH + headBase + 1] = sd1;
                }
            }
    }

    if (FUSE2) {
        // full-row (64 col) dot with a_src/a_dst; cross-warp smem reduction
        float* sP = reinterpret_cast<float*>(&sA[0][0]);   // [128][4]
        __syncthreads();
        float asc[NT * 2], adc[NT * 2];
        #pragma unroll
        for (int nt = 0; nt < NT; nt++)
            #pragma unroll
            for (int j = 0; j < 2; j++) {
                int col = warpN * (BN / 2) + nt * 8 + (lane & 3) * 2 + j;
                asc[nt * 2 + j] = a_src[col];
                adc[nt * 2 + j] = a_dst[col];
            }
        #pragma unroll
        for (int mt = 0; mt < 2; mt++)
            #pragma unroll
            for (int half = 0; half < 2; half++) {
                float ss = 0.f, sd = 0.f;
                #pragma unroll
                for (int nt = 0; nt < NT; nt++)
                    #pragma unroll
                    for (int j = 0; j < 2; j++) {
                        float v = c[mt][nt][half * 2 + j];
                        ss += v * asc[nt * 2 + j];
                        sd += v * adc[nt * 2 + j];
                    }
                #pragma unroll
                for (int o = 1; o <= 2; o <<= 1) {
                    ss += __shfl_xor_sync(0xffffffffu, ss, o);
                    sd += __shfl_xor_sync(0xffffffffu, sd, o);
                }
                if ((lane & 3) == 0) {
                    int rl = warpM * 32 + mt * 16 + (lane >> 2) + half * 8;
                    sP[rl * 4 + warpN * 2 + 0] = ss;
                    sP[rl * 4 + warpN * 2 + 1] = sd;
                }
            }
        __syncthreads();
        if (tid < 128) {
            int row = rowBase + tid;
            if (row < M) {
                g_as[row] = sP[tid * 4 + 0] + sP[tid * 4 + 2];
                g_ad[row] = sP[tid * 4 + 1] + sP[tid * 4 + 3];
            }
        }
    }
}

// ---------------- layer-1 aggregation (warp per dst, pipelined) ----------------
__global__ void __launch_bounds__(256) agg1_kernel(const float* __restrict__ b1) {
    int dst = (blockIdx.x * blockDim.x + threadIdx.x) >> 5;
    int lane = threadIdx.x & 31;
    if (dst >= GN) return;
    const int head = lane >> 2;

    const float ad = g_ad1[(size_t)dst * GH + head];
    const int rs = g_rowptr[dst];
    const int re = g_rowptr[dst + 1];

    // prefetch first edge
    int src0 = (rs < re) ? g_srcs[rs] : 0;
    uint4 u = *reinterpret_cast<const uint4*>(g_h1b + (size_t)src0 * GF1 + lane * 8);
    float av = g_as1[(size_t)src0 * GH + head];

    float acc[8];
    float den;
    {   // self loop
        float w = __expf(lrelu(g_as1[(size_t)dst * GH + head] + ad));
        den = w;
        uint4 us = *reinterpret_cast<const uint4*>(g_h1b + (size_t)dst * GF1 + lane * 8);
        float2 f0 = unpack_bf16x2(us.x), f1 = unpack_bf16x2(us.y);
        float2 f2 = unpack_bf16x2(us.z), f3 = unpack_bf16x2(us.w);
        acc[0] = w * f0.x; acc[1] = w * f0.y; acc[2] = w * f1.x; acc[3] = w * f1.y;
        acc[4] = w * f2.x; acc[5] = w * f2.y; acc[6] = w * f3.x; acc[7] = w * f3.y;
    }
    for (int e = rs; e < re; e++) {
        uint4 uc = u;
        float ac = av;
        if (e + 1 < re) {
            int s2 = g_srcs[e + 1];
            u = *reinterpret_cast<const uint4*>(g_h1b + (size_t)s2 * GF1 + lane * 8);
            av = g_as1[(size_t)s2 * GH + head];
        }
        float w = __expf(lrelu(ac + ad));
        den += w;
        float2 f0 = unpack_bf16x2(uc.x), f1 = unpack_bf16x2(uc.y);
        float2 f2 = unpack_bf16x2(uc.z), f3 = unpack_bf16x2(uc.w);
        acc[0] += w * f0.x; acc[1] += w * f0.y; acc[2] += w * f1.x; acc[3] += w * f1.y;
        acc[4] += w * f2.x; acc[5] += w * f2.y; acc[6] += w * f3.x; acc[7] += w * f3.y;
    }
    float inv = 1.f / den;
    float4 bb0 = *reinterpret_cast<const float4*>(b1 + lane * 8);
    float4 bb1 = *reinterpret_cast<const float4*>(b1 + lane * 8 + 4);
    float bv[8] = {bb0.x, bb0.y, bb0.z, bb0.w, bb1.x, bb1.y, bb1.z, bb1.w};
    uint4 st;
    uint32_t* stp = reinterpret_cast<uint32_t*>(&st);
    #pragma unroll
    for (int p = 0; p < 4; p++) {
        float v0 = fmaxf(acc[2 * p] * inv + bv[2 * p], 0.f);
        float v1 = fmaxf(acc[2 * p + 1] * inv + bv[2 * p + 1], 0.f);
        stp[p] = pack_bf16x2(v0, v1);
    }
    *reinterpret_cast<uint4*>(g_out1b + (size_t)dst * GF1 + lane * 8) = st;
}

// ---------------- layer-2 aggregation + bias + log_softmax ---------------------
__global__ void __launch_bounds__(256) agg2_kernel(const float* __restrict__ b2,
                                                   float* __restrict__ out) {
    int dst = (blockIdx.x * blockDim.x + threadIdx.x) >> 5;
    int lane = threadIdx.x & 31;
    if (dst >= GN) return;

    const float ad = g_ad2[dst];
    const int rs = g_rowptr[dst];
    const int re = g_rowptr[dst + 1];

    int src0 = (rs < re) ? g_srcs[rs] : 0;
    uint32_t u = *reinterpret_cast<const uint32_t*>(g_h2b + (size_t)src0 * GOUT + 2 * lane);
    float av = g_as2[src0];

    float den, a0, a1;
    {
        float w = __expf(lrelu(g_as2[dst] + ad));
        den = w;
        uint32_t us = *reinterpret_cast<const uint32_t*>(g_h2b + (size_t)dst * GOUT + 2 * lane);
        float2 f = unpack_bf16x2(us);
        a0 = w * f.x;
        a1 = w * f.y;
    }
    for (int e = rs; e < re; e++) {
        uint32_t uc = u;
        float ac = av;
        if (e + 1 < re) {
            int s2 = g_srcs[e + 1];
            u = *reinterpret_cast<const uint32_t*>(g_h2b + (size_t)s2 * GOUT + 2 * lane);
            av = g_as2[s2];
        }
        float w = __expf(lrelu(ac + ad));
        den += w;
        float2 f = unpack_bf16x2(uc);
        a0 += w * f.x;
        a1 += w * f.y;
    }
    float2 bb = *reinterpret_cast<const float2*>(b2 + 2 * lane);
    float inv = 1.f / den;
    float v0 = a0 * inv + bb.x;
    float v1 = a1 * inv + bb.y;

    float m = fmaxf(v0, v1);
    #pragma unroll
    for (int o = 16; o; o >>= 1) m = fmaxf(m, __shfl_xor_sync(0xffffffffu, m, o));
    float s = __expf(v0 - m) + __expf(v1 - m);
    #pragma unroll
    for (int o = 16; o; o >>= 1) s += __shfl_xor_sync(0xffffffffu, s, o);
    float ls = __logf(s) + m;

    float2 st = make_float2(v0 - ls, v1 - ls);
    *reinterpret_cast<float2*>(out + (size_t)dst * GOUT + 2 * lane) = st;
}

// ---------------- launch --------------------------------------------------------
extern "C" void kernel_launch(void* const* d_in, const int* in_sizes, int n_in,
                              void* d_out, int out_size) {
    const float* x      = (const float*)d_in[0];
    const int*   ei     = (const int*)d_in[1];
    const float* W1     = (const float*)d_in[2];
    const float* a_src1 = (const float*)d_in[3];
    const float* a_dst1 = (const float*)d_in[4];
    const float* b1     = (const float*)d_in[5];
    const float* W2     = (const float*)d_in[6];
    const float* a_src2 = (const float*)d_in[7];
    const float* a_dst2 = (const float*)d_in[8];
    const float* b2     = (const float*)d_in[9];
    float* out = (float*)d_out;
    const int E = in_sizes[1] / 2;

    __nv_bfloat16 *xbp, *w1p, *w2p, *h1p, *out1p, *h2p;
    float *as1p, *ad1p, *as2p, *ad2p;
    void* cntp;
    cudaGetSymbolAddress((void**)&xbp, g_xb);
    cudaGetSymbolAddress((void**)&w1p, g_w1b);
    cudaGetSymbolAddress((void**)&w2p, g_w2b);
    cudaGetSymbolAddress((void**)&h1p, g_h1b);
    cudaGetSymbolAddress((void**)&out1p, g_out1b);
    cudaGetSymbolAddress((void**)&h2p, g_h2b);
    cudaGetSymbolAddress((void**)&as1p, g_as1);
    cudaGetSymbolAddress((void**)&ad1p, g_ad1);
    cudaGetSymbolAddress((void**)&as2p, g_as2);
    cudaGetSymbolAddress((void**)&ad2p, g_ad2);
    cudaGetSymbolAddress(&cntp, g_cnt);

    // CSR build + bf16 conversion (independent chains, same stream)
    cudaMemsetAsync(cntp, 0, GN * sizeof(int));
    convert_kernel<<<800, 256>>>(x, W1, W2);
    hist_kernel<<<(E / 4 + 4 + 255) / 256, 256>>>(ei, E);
    block_sum_kernel<<<NB, 256>>>();
    scan_apply_kernel<<<NB, 256>>>();
    scatter_kernel<<<(E / 4 + 4 + 255) / 256, 256>>>(ei, E);

    // layer 1: bf16 cp.async GEMM with fused alpha1 epilogue
    gemm_async_kernel<128, true, false>
        <<<dim3(GF1 / 128, (GN + 127) / 128), 256>>>(
            xbp, w1p, h1p, GN, GIN, GF1, a_src1, a_dst1, as1p, ad1p);
    agg1_kernel<<<(GN + 7) / 8, 256>>>(b1);

    // layer 2: bf16 cp.async GEMM with fused alpha2 epilogue
    gemm_async_kernel<64, false, true>
        <<<dim3(GOUT / 64, (GN + 127) / 128), 256>>>(
            out1p, w2p, h2p, GN, GF1, GOUT, a_src2, a_dst2, as2p, ad2p);
    agg2_kernel<<<(GN + 7) / 8, 256>>>(b2, out);
}

// round 7
// speedup vs baseline: 3.4135x; 1.0110x over previous
#include <cuda_runtime.h>
#include <cuda_bf16.h>
#include <cstdint>

#define GN 50000      // nodes
#define GE 800000     // edges (without self loops)
#define GIN 256       // in_dim
#define GH 8          // heads layer1
#define GHID 32       // hidden per head
#define GF1 256       // H*HID
#define GOUT 64       // classes
#define NB  ((GN + 255) / 256)

// ---------------- scratch (device globals) -------------------------------------
__device__ __nv_bfloat16 g_w1b[GIN * GF1];           // W1 bf16
__device__ __nv_bfloat16 g_w2b[GF1 * GOUT];          // W2 bf16
__device__ __nv_bfloat16 g_h1b[(size_t)GN * GF1];    // x @ W1, bf16
__device__ __nv_bfloat16 g_out1b[(size_t)GN * GF1];  // relu(gat1), bf16
__device__ __nv_bfloat16 g_h2b[(size_t)GN * GOUT];   // out1 @ W2, bf16
__device__ float g_as1[(size_t)GN * GH];
__device__ float g_ad1[(size_t)GN * GH];
__device__ float g_as2[GN];
__device__ float g_ad2[GN];
__device__ int   g_cnt[GN];        // histogram -> cursor
__device__ int   g_rowptr[GN + 1];
__device__ int   g_srcs[GE];       // src ids bucketed by dst
__device__ int   g_bsum[NB + 1];

__device__ __forceinline__ float lrelu(float x) { return fmaxf(x, 0.2f * x); }

__device__ __forceinline__ uint32_t pack_bf16x2(float lo, float hi) {
    uint32_t r;
    asm("cvt.rn.bf16x2.f32 %0, %1, %2;" : "=r"(r) : "f"(hi), "f"(lo));
    return r;
}
__device__ __forceinline__ float2 unpack_bf16x2(uint32_t u) {
    float2 f;
    f.x = __uint_as_float(u << 16);
    f.y = __uint_as_float(u & 0xffff0000u);
    return f;
}
__device__ __forceinline__ uint32_t smem_u32(const void* p) {
    return (uint32_t)__cvta_generic_to_shared(p);
}
__device__ __forceinline__ void cp_async16(uint32_t dst, const void* src, bool pred) {
    int sz = pred ? 16 : 0;
    asm volatile("cp.async.cg.shared.global [%0], [%1], 16, %2;\n"
                 :: "r"(dst), "l"(src), "r"(sz));
}
__device__ __forceinline__ void cp_commit() {
    asm volatile("cp.async.commit_group;\n");
}
__device__ __forceinline__ void ldsm_x4(uint32_t* r, uint32_t addr) {
    asm volatile("ldmatrix.sync.aligned.m8n8.x4.shared.b16 {%0,%1,%2,%3}, [%4];\n"
                 : "=r"(r[0]), "=r"(r[1]), "=r"(r[2]), "=r"(r[3]) : "r"(addr));
}
__device__ __forceinline__ void ldsm_x4_t(uint32_t* r, uint32_t addr) {
    asm volatile("ldmatrix.sync.aligned.m8n8.x4.trans.shared.b16 {%0,%1,%2,%3}, [%4];\n"
                 : "=r"(r[0]), "=r"(r[1]), "=r"(r[2]), "=r"(r[3]) : "r"(addr));
}
__device__ __forceinline__ void mma_bf16(float* c, const uint32_t* a, uint32_t b0, uint32_t b1) {
    asm volatile(
        "mma.sync.aligned.m16n8k16.row.col.f32.bf16.bf16.f32 "
        "{%0,%1,%2,%3},{%4,%5,%6,%7},{%8,%9},{%0,%1,%2,%3};\n"
        : "+f"(c[0]), "+f"(c[1]), "+f"(c[2]), "+f"(c[3])
        : "r"(a[0]), "r"(a[1]), "r"(a[2]), "r"(a[3]), "r"(b0), "r"(b1));
}

// ---------------- prep: histogram (int4) + W1/W2 fp32->bf16 --------------------
__global__ void prep_kernel(const int* __restrict__ ei, int E,
                            const float* __restrict__ W1,
                            const float* __restrict__ W2) {
    int i = blockIdx.x * blockDim.x + threadIdx.x;
    int n4 = E >> 2;
    if (i < n4) {
        int4 d = reinterpret_cast<const int4*>(ei + E)[i];
        atomicAdd(&g_cnt[d.x], 1);
        atomicAdd(&g_cnt[d.y], 1);
        atomicAdd(&g_cnt[d.z], 1);
        atomicAdd(&g_cnt[d.w], 1);
    } else if (i < n4 + (E & 3)) {
        atomicAdd(&g_cnt[ei[E + n4 * 4 + (i - n4)]], 1);
    }
    // W conversion (grid-stride over both)
    int stride = gridDim.x * blockDim.x;
    const int T1 = GIN * GF1 / 8;
    for (int t = i; t < T1; t += stride) {
        float4 v0 = reinterpret_cast<const float4*>(W1)[t * 2];
        float4 v1 = reinterpret_cast<const float4*>(W1)[t * 2 + 1];
        uint4 u = make_uint4(pack_bf16x2(v0.x, v0.y), pack_bf16x2(v0.z, v0.w),
                             pack_bf16x2(v1.x, v1.y), pack_bf16x2(v1.z, v1.w));
        reinterpret_cast<uint4*>(g_w1b)[t] = u;
    }
    const int T2 = GF1 * GOUT / 8;
    for (int t = i; t < T2; t += stride) {
        float4 v0 = reinterpret_cast<const float4*>(W2)[t * 2];
        float4 v1 = reinterpret_cast<const float4*>(W2)[t * 2 + 1];
        uint4 u = make_uint4(pack_bf16x2(v0.x, v0.y), pack_bf16x2(v0.z, v0.w),
                             pack_bf16x2(v1.x, v1.y), pack_bf16x2(v1.z, v1.w));
        reinterpret_cast<uint4*>(g_w2b)[t] = u;
    }
}

__global__ void block_sum_kernel() {
    __shared__ int ws[8];
    int i = blockIdx.x * 256 + threadIdx.x;
    int v = (i < GN) ? g_cnt[i] : 0;
    int s = v;
    #pragma unroll
    for (int o = 16; o; o >>= 1) s += __shfl_xor_sync(0xffffffffu, s, o);
    if ((threadIdx.x & 31) == 0) ws[threadIdx.x >> 5] = s;
    __syncthreads();
    if (threadIdx.x < 8) {
        int t = ws[threadIdx.x];
        #pragma unroll
        for (int o = 4; o; o >>= 1) t += __shfl_xor_sync(0xffu, t, o);
        if (threadIdx.x == 0) g_bsum[blockIdx.x] = t;
    }
}

__global__ void scan_apply_kernel() {
    __shared__ int ws[8];
    __shared__ int s_off;
    int tid = threadIdx.x, lane = tid & 31, wid = tid >> 5;

    int a = 0;
    for (int j = tid; j < blockIdx.x; j += 256) a += g_bsum[j];
    #pragma unroll
    for (int o = 16; o; o >>= 1) a += __shfl_xor_sync(0xffffffffu, a, o);
    if (lane == 0) ws[wid] = a;
    __syncthreads();
    if (tid == 0) {
        int t = 0;
        #pragma unroll
        for (int k = 0; k < 8; k++) t += ws[k];
        s_off = t;
    }
    __syncthreads();

    int i = blockIdx.x * 256 + tid;
    int v = (i < GN) ? g_cnt[i] : 0;
    int s = v;
    #pragma unroll
    for (int o = 1; o < 32; o <<= 1) {
        int t = __shfl_up_sync(0xffffffffu, s, o);
        if (lane >= o) s += t;
    }
    if (lane == 31) ws[wid] = s;
    __syncthreads();
    if (wid == 0 && lane < 8) {
        int t = ws[lane];
        #pragma unroll
        for (int o = 1; o < 8; o <<= 1) {
            int u = __shfl_up_sync(0xffu, t, o);
            if (lane >= o) t += u;
        }
        ws[lane] = t;
    }
    __syncthreads();
    int incl = s + (wid ? ws[wid - 1] : 0) + s_off;
    if (i < GN) {
        g_rowptr[i + 1] = incl;
        g_cnt[i] = incl - v;   // exclusive -> scatter cursor
    }
    if (i == 0) g_rowptr[0] = 0;
}

__global__ void scatter_kernel(const int* __restrict__ ei, int E) {
    int i = blockIdx.x * blockDim.x + threadIdx.x;
    int n4 = E >> 2;
    if (i < n4) {
        int4 sv = reinterpret_cast<const int4*>(ei)[i];
        int4 dv = reinterpret_cast<const int4*>(ei + E)[i];
        g_srcs[atomicAdd(&g_cnt[dv.x], 1)] = sv.x;
        g_srcs[atomicAdd(&g_cnt[dv.y], 1)] = sv.y;
        g_srcs[atomicAdd(&g_cnt[dv.z], 1)] = sv.z;
        g_srcs[atomicAdd(&g_cnt[dv.w], 1)] = sv.w;
    } else if (i < n4 + (E & 3)) {
        int e = n4 * 4 + (i - n4);
        g_srcs[atomicAdd(&g_cnt[ei[E + e]], 1)] = ei[e];
    }
}

// ---------------- GEMM1: A fp32 (x), B bf16 (W1), BM=64 BN=256 -----------------
// Warps 2(M) x 4(N). A read ONCE (single column-block). A staged via
// LDG.float4 -> cvt -> STS (issued a full stage early); B via cp.async.
// Fused alpha1 epilogue: per-warp slice = 64 cols = 2 heads.
__global__ void __launch_bounds__(256) gemm1_kernel(
    const float* __restrict__ A, const __nv_bfloat16* __restrict__ B,
    __nv_bfloat16* __restrict__ C,
    const float* __restrict__ a_src, const float* __restrict__ a_dst,
    float* __restrict__ g_as, float* __restrict__ g_ad) {
    constexpr int BN = 256, SBS = BN + 8;
    constexpr int A_ELEM = 64 * 40;
    constexpr int B_ELEM = 32 * SBS;
    __shared__ __align__(16) __nv_bfloat16 sA[2][A_ELEM];
    __shared__ __align__(16) __nv_bfloat16 sB[2][B_ELEM];

    const int tid = threadIdx.x, lane = tid & 31, wid = tid >> 5;
    const int warpM = wid & 1, warpN = wid >> 1;      // 2 x 4
    const int rowBase = blockIdx.x * 64;
    const int wcb = warpN * 64;

    const uint32_t sAu = smem_u32(&sA[0][0]), sBu = smem_u32(&sB[0][0]);
    const int aRow = warpM * 32 + (lane & 7) + ((lane >> 3) & 1) * 8;
    const uint32_t aAddr = sAu + (uint32_t)(aRow * 40 + ((lane >> 4) * 8)) * 2;
    const int bRow = (lane & 7) + ((lane >> 3) & 1) * 8;
    const uint32_t bAddr = sBu + (uint32_t)(bRow * SBS + wcb + (lane >> 4) * 8) * 2;

    // A staging indices: 64x32 fp32 = 512 float4, 2 per thread
    const int ar0 = tid >> 3, ac0 = (tid & 7) * 4;            // f = tid
    const int ar1 = (tid + 256) >> 3, ac1 = ac0;              // f = tid+256

    auto ldA = [&](float4* r, int k0) {
        int row0 = rowBase + ar0, row1 = rowBase + ar1;
        r[0] = (row0 < GN) ? *reinterpret_cast<const float4*>(A + (size_t)row0 * GIN + k0 + ac0)
                           : make_float4(0.f, 0.f, 0.f, 0.f);
        r[1] = (row1 < GN) ? *reinterpret_cast<const float4*>(A + (size_t)row1 * GIN + k0 + ac1)
                           : make_float4(0.f, 0.f, 0.f, 0.f);
    };
    auto stA = [&](int buf, const float4* r) {
        uint2 p0 = make_uint2(pack_bf16x2(r[0].x, r[0].y), pack_bf16x2(r[0].z, r[0].w));
        uint2 p1 = make_uint2(pack_bf16x2(r[1].x, r[1].y), pack_bf16x2(r[1].z, r[1].w));
        *reinterpret_cast<uint2*>(&sA[buf][ar0 * 40 + ac0]) = p0;
        *reinterpret_cast<uint2*>(&sA[buf][ar1 * 40 + ac1]) = p1;
    };
    auto stageB = [&](int buf, int k0) {
        #pragma unroll
        for (int i2 = 0; i2 < 4; i2++) {
            int f = tid + i2 * 256;
            int krow = f >> 5, c8 = (f & 31) * 8;
            uint32_t dst = sBu + (uint32_t)(buf * B_ELEM + krow * SBS + c8) * 2;
            cp_async16(dst, B + (size_t)(k0 + krow) * BN + c8, true);
        }
    };

    float c[2][8][4];
    #pragma unroll
    for (int i = 0; i < 2; i++)
        #pragma unroll
        for (int j = 0; j < 8; j++)
            #pragma unroll
            for (int q = 0; q < 4; q++) c[i][j][q] = 0.f;

    constexpr int S = GIN / 32;
    float4 ra[2];
    ldA(ra, 0);
    stA(0, ra);
    stageB(0, 0);
    cp_commit();

    float4 rn[2];
    for (int s = 0; s < S; s++) {
        const int buf = s & 1;
        if (s + 1 < S) {
            ldA(rn, (s + 1) * 32);                 // LDG early: full stage to cover
            stageB(buf ^ 1, (s + 1) * 32);
            cp_commit();
            asm volatile("cp.async.wait_group 1;\n");
        } else {
            asm volatile("cp.async.wait_group 0;\n");
        }
        __syncthreads();
        const uint32_t aB = aAddr + buf * A_ELEM * 2;
        const uint32_t bB = bAddr + buf * B_ELEM * 2;
        #pragma unroll
        for (int ks = 0; ks < 2; ks++) {
            uint32_t a[2][4];
            #pragma unroll
            for (int mt = 0; mt < 2; mt++)
                ldsm_x4(a[mt], aB + (uint32_t)(mt * 16 * 40 + ks * 16) * 2);
            uint32_t b[4][4];
            #pragma unroll
            for (int np = 0; np < 4; np++)
                ldsm_x4_t(b[np], bB + (uint32_t)(ks * 16 * SBS + np * 16) * 2);
            #pragma unroll
            for (int mt = 0; mt < 2; mt++)
                #pragma unroll
                for (int nt = 0; nt < 8; nt++) {
                    int np = nt >> 1;
                    mma_bf16(c[mt][nt], a[mt], b[np][(nt & 1) * 2], b[np][(nt & 1) * 2 + 1]);
                }
        }
        if (s + 1 < S) stA(buf ^ 1, rn);
        __syncthreads();
    }

    // epilogue: store C bf16
    #pragma unroll
    for (int mt = 0; mt < 2; mt++)
        #pragma unroll
        for (int half = 0; half < 2; half++) {
            int row = rowBase + warpM * 32 + mt * 16 + (lane >> 2) + half * 8;
            if (row < GN) {
                #pragma unroll
                for (int nt = 0; nt < 8; nt++) {
                    int col = wcb + nt * 8 + (lane & 3) * 2;
                    uint32_t u = pack_bf16x2(c[mt][nt][half * 2], c[mt][nt][half * 2 + 1]);
                    *reinterpret_cast<uint32_t*>(C + (size_t)row * GF1 + col) = u;
                }
            }
        }

    // fused alpha1: warp slice 64 cols = heads {2*warpN, 2*warpN+1}
    float asc[16], adc[16];
    #pragma unroll
    for (int nt = 0; nt < 8; nt++)
        #pragma unroll
        for (int j = 0; j < 2; j++) {
            int col = wcb + nt * 8 + (lane & 3) * 2 + j;
            asc[nt * 2 + j] = a_src[col];
            adc[nt * 2 + j] = a_dst[col];
        }
    int headBase = wcb >> 5;
    #pragma unroll
    for (int mt = 0; mt < 2; mt++)
        #pragma unroll
        for (int half = 0; half < 2; half++) {
            int row = rowBase + warpM * 32 + mt * 16 + (lane >> 2) + half * 8;
            float ss0 = 0.f, ss1 = 0.f, sd0 = 0.f, sd1 = 0.f;
            #pragma unroll
            for (int nt = 0; nt < 8; nt++)
                #pragma unroll
                for (int j = 0; j < 2; j++) {
                    float v = c[mt][nt][half * 2 + j];
                    if (nt < 4) { ss0 += v * asc[nt * 2 + j]; sd0 += v * adc[nt * 2 + j]; }
                    else        { ss1 += v * asc[nt * 2 + j]; sd1 += v * adc[nt * 2 + j]; }
                }
            #pragma unroll
            for (int o = 1; o <= 2; o <<= 1) {
                ss0 += __shfl_xor_sync(0xffffffffu, ss0, o);
                ss1 += __shfl_xor_sync(0xffffffffu, ss1, o);
                sd0 += __shfl_xor_sync(0xffffffffu, sd0, o);
                sd1 += __shfl_xor_sync(0xffffffffu, sd1, o);
            }
            if ((lane & 3) == 0 && row < GN) {
                g_as[(size_t)row * GH + headBase]     = ss0;
                g_as[(size_t)row * GH + headBase + 1] = ss1;
                g_ad[(size_t)row * GH + headBase]     = sd0;
                g_ad[(size_t)row * GH + headBase + 1] = sd1;
            }
        }
}

// ---------------- GEMM2: bf16 A (out1), BN=64, fused alpha2 --------------------
// BM=128, 256 threads, warps 4(M) x 2(N), cp.async double-buffered.
__global__ void __launch_bounds__(256) gemm2_kernel(
    const __nv_bfloat16* __restrict__ A, const __nv_bfloat16* __restrict__ B,
    __nv_bfloat16* __restrict__ C, int M, int K, int Nc,
    const float* __restrict__ a_src, const float* __restrict__ a_dst,
    float* __restrict__ g_as, float* __restrict__ g_ad) {
    constexpr int BN = 64, NT = 4, NP = 2, SBS = BN + 8;
    constexpr int A_ELEM = 128 * 40;
    constexpr int B_ELEM = 32 * SBS;
    __shared__ __align__(16) __nv_bfloat16 sA[2][A_ELEM];
    __shared__ __align__(16) __nv_bfloat16 sB[2][B_ELEM];

    const int tid = threadIdx.x, lane = tid & 31, wid = tid >> 5;
    const int warpM = wid & 3, warpN = wid >> 2;
    const int rowBase = blockIdx.y * 128;
    const int wcb = warpN * (BN / 2);

    const uint32_t sAu = smem_u32(&sA[0][0]), sBu = smem_u32(&sB[0][0]);
    const int aRow = warpM * 32 + (lane & 7) + ((lane >> 3) & 1) * 8;
    const uint32_t aAddr = sAu + (uint32_t)(aRow * 40 + ((lane >> 4) * 8)) * 2;
    const int bRow = (lane & 7) + ((lane >> 3) & 1) * 8;
    const uint32_t bAddr = sBu + (uint32_t)(bRow * SBS + wcb + (lane >> 4) * 8) * 2;

    auto stageA = [&](int buf, int k0) {
        #pragma unroll
        for (int i2 = 0; i2 < 2; i2++) {
            int f = tid + i2 * 256;
            int r = f >> 2, c8 = (f & 3) * 8;
            int row = rowBase + r;
            uint32_t dst = sAu + (uint32_t)(buf * A_ELEM + r * 40 + c8) * 2;
            cp_async16(dst, A + (size_t)row * K + k0 + c8, row < M);
        }
    };
    auto stageB = [&](int buf, int k0) {
        int krow = tid >> 3, c8 = (tid & 7) * 8;
        uint32_t dst = sBu + (uint32_t)(buf * B_ELEM + krow * SBS + c8) * 2;
        cp_async16(dst, B + (size_t)(k0 + krow) * Nc + c8, true);
    };

    float c[2][NT][4];
    #pragma unroll
    for (int i = 0; i < 2; i++)
        #pragma unroll
        for (int j = 0; j < NT; j++)
            #pragma unroll
            for (int q = 0; q < 4; q++) c[i][j][q] = 0.f;

    const int S = K / 32;
    stageA(0, 0);
    stageB(0, 0);
    cp_commit();

    for (int s = 0; s < S; s++) {
        const int buf = s & 1;
        if (s + 1 < S) {
            stageA(buf ^ 1, (s + 1) * 32);
            stageB(buf ^ 1, (s + 1) * 32);
            cp_commit();
            asm volatile("cp.async.wait_group 1;\n");
        } else {
            asm volatile("cp.async.wait_group 0;\n");
        }
        __syncthreads();
        const uint32_t aB = aAddr + buf * A_ELEM * 2;
        const uint32_t bB = bAddr + buf * B_ELEM * 2;
        #pragma unroll
        for (int ks = 0; ks < 2; ks++) {
            uint32_t a[2][4];
            #pragma unroll
            for (int mt = 0; mt < 2; mt++)
                ldsm_x4(a[mt], aB + (uint32_t)(mt * 16 * 40 + ks * 16) * 2);
            uint32_t b[NP][4];
            #pragma unroll
            for (int np = 0; np < NP; np++)
                ldsm_x4_t(b[np], bB + (uint32_t)(ks * 16 * SBS + np * 16) * 2);
            #pragma unroll
            for (int mt = 0; mt < 2; mt++)
                #pragma unroll
                for (int nt = 0; nt < NT; nt++) {
                    int np = nt >> 1;
                    mma_bf16(c[mt][nt], a[mt], b[np][(nt & 1) * 2], b[np][(nt & 1) * 2 + 1]);
                }
        }
        __syncthreads();
    }

    #pragma unroll
    for (int mt = 0; mt < 2; mt++)
        #pragma unroll
        for (int half = 0; half < 2; half++) {
            int row = rowBase + warpM * 32 + mt * 16 + (lane >> 2) + half * 8;
            if (row < M) {
                #pragma unroll
                for (int nt = 0; nt < NT; nt++) {
                    int col = wcb + nt * 8 + (lane & 3) * 2;
                    uint32_t u = pack_bf16x2(c[mt][nt][half * 2], c[mt][nt][half * 2 + 1]);
                    *reinterpret_cast<uint32_t*>(C + (size_t)row * Nc + col) = u;
                }
            }
        }

    // fused alpha2: full-row dot, cross-warp smem reduction
    float* sP = reinterpret_cast<float*>(&sA[0][0]);   // [128][4]
    __syncthreads();
    float asc[NT * 2], adc[NT * 2];
    #pragma unroll
    for (int nt = 0; nt < NT; nt++)
        #pragma unroll
        for (int j = 0; j < 2; j++) {
            int col = wcb + nt * 8 + (lane & 3) * 2 + j;
            asc[nt * 2 + j] = a_src[col];
            adc[nt * 2 + j] = a_dst[col];
        }
    #pragma unroll
    for (int mt = 0; mt < 2; mt++)
        #pragma unroll
        for (int half = 0; half < 2; half++) {
            float ss = 0.f, sd = 0.f;
            #pragma unroll
            for (int nt = 0; nt < NT; nt++)
                #pragma unroll
                for (int j = 0; j < 2; j++) {
                    float v = c[mt][nt][half * 2 + j];
                    ss += v * asc[nt * 2 + j];
                    sd += v * adc[nt * 2 + j];
                }
            #pragma unroll
            for (int o = 1; o <= 2; o <<= 1) {
                ss += __shfl_xor_sync(0xffffffffu, ss, o);
                sd += __shfl_xor_sync(0xffffffffu, sd, o);
            }
            if ((lane & 3) == 0) {
                int rl = warpM * 32 + mt * 16 + (lane >> 2) + half * 8;
                sP[rl * 4 + warpN * 2 + 0] = ss;
                sP[rl * 4 + warpN * 2 + 1] = sd;
            }
        }
    __syncthreads();
    if (tid < 128) {
        int row = rowBase + tid;
        if (row < M) {
            g_as[row] = sP[tid * 4 + 0] + sP[tid * 4 + 2];
            g_ad[row] = sP[tid * 4 + 1] + sP[tid * 4 + 3];
        }
    }
}

// ---------------- layer-1 aggregation (warp per dst, pipelined) ----------------
__global__ void __launch_bounds__(256) agg1_kernel(const float* __restrict__ b1) {
    int dst = (blockIdx.x * blockDim.x + threadIdx.x) >> 5;
    int lane = threadIdx.x & 31;
    if (dst >= GN) return;
    const int head = lane >> 2;

    const float ad = g_ad1[(size_t)dst * GH + head];
    const int rs = g_rowptr[dst];
    const int re = g_rowptr[dst + 1];

    int src0 = (rs < re) ? g_srcs[rs] : 0;
    uint4 u = *reinterpret_cast<const uint4*>(g_h1b + (size_t)src0 * GF1 + lane * 8);
    float av = g_as1[(size_t)src0 * GH + head];

    float acc[8];
    float den;
    {   // self loop
        float w = __expf(lrelu(g_as1[(size_t)dst * GH + head] + ad));
        den = w;
        uint4 us = *reinterpret_cast<const uint4*>(g_h1b + (size_t)dst * GF1 + lane * 8);
        float2 f0 = unpack_bf16x2(us.x), f1 = unpack_bf16x2(us.y);
        float2 f2 = unpack_bf16x2(us.z), f3 = unpack_bf16x2(us.w);
        acc[0] = w * f0.x; acc[1] = w * f0.y; acc[2] = w * f1.x; acc[3] = w * f1.y;
        acc[4] = w * f2.x; acc[5] = w * f2.y; acc[6] = w * f3.x; acc[7] = w * f3.y;
    }
    for (int e = rs; e < re; e++) {
        uint4 uc = u;
        float ac = av;
        if (e + 1 < re) {
            int s2 = g_srcs[e + 1];
            u = *reinterpret_cast<const uint4*>(g_h1b + (size_t)s2 * GF1 + lane * 8);
            av = g_as1[(size_t)s2 * GH + head];
        }
        float w = __expf(lrelu(ac + ad));
        den += w;
        float2 f0 = unpack_bf16x2(uc.x), f1 = unpack_bf16x2(uc.y);
        float2 f2 = unpack_bf16x2(uc.z), f3 = unpack_bf16x2(uc.w);
        acc[0] += w * f0.x; acc[1] += w * f0.y; acc[2] += w * f1.x; acc[3] += w * f1.y;
        acc[4] += w * f2.x; acc[5] += w * f2.y; acc[6] += w * f3.x; acc[7] += w * f3.y;
    }
    float inv = 1.f / den;
    float4 bb0 = *reinterpret_cast<const float4*>(b1 + lane * 8);
    float4 bb1 = *reinterpret_cast<const float4*>(b1 + lane * 8 + 4);
    float bv[8] = {bb0.x, bb0.y, bb0.z, bb0.w, bb1.x, bb1.y, bb1.z, bb1.w};
    uint4 st;
    uint32_t* stp = reinterpret_cast<uint32_t*>(&st);
    #pragma unroll
    for (int p = 0; p < 4; p++) {
        float v0 = fmaxf(acc[2 * p] * inv + bv[2 * p], 0.f);
        float v1 = fmaxf(acc[2 * p + 1] * inv + bv[2 * p + 1], 0.f);
        stp[p] = pack_bf16x2(v0, v1);
    }
    *reinterpret_cast<uint4*>(g_out1b + (size_t)dst * GF1 + lane * 8) = st;
}

// ---------------- layer-2 aggregation + bias + log_softmax ---------------------
__global__ void __launch_bounds__(256) agg2_kernel(const float* __restrict__ b2,
                                                   float* __restrict__ out) {
    int dst = (blockIdx.x * blockDim.x + threadIdx.x) >> 5;
    int lane = threadIdx.x & 31;
    if (dst >= GN) return;

    const float ad = g_ad2[dst];
    const int rs = g_rowptr[dst];
    const int re = g_rowptr[dst + 1];

    int src0 = (rs < re) ? g_srcs[rs] : 0;
    uint32_t u = *reinterpret_cast<const uint32_t*>(g_h2b + (size_t)src0 * GOUT + 2 * lane);
    float av = g_as2[src0];

    float den, a0, a1;
    {
        float w = __expf(lrelu(g_as2[dst] + ad));
        den = w;
        uint32_t us = *reinterpret_cast<const uint32_t*>(g_h2b + (size_t)dst * GOUT + 2 * lane);
        float2 f = unpack_bf16x2(us);
        a0 = w * f.x;
        a1 = w * f.y;
    }
    for (int e = rs; e < re; e++) {
        uint32_t uc = u;
        float ac = av;
        if (e + 1 < re) {
            int s2 = g_srcs[e + 1];
            u = *reinterpret_cast<const uint32_t*>(g_h2b + (size_t)s2 * GOUT + 2 * lane);
            av = g_as2[s2];
        }
        float w = __expf(lrelu(ac + ad));
        den += w;
        float2 f = unpack_bf16x2(uc);
        a0 += w * f.x;
        a1 += w * f.y;
    }
    float2 bb = *reinterpret_cast<const float2*>(b2 + 2 * lane);
    float inv = 1.f / den;
    float v0 = a0 * inv + bb.x;
    float v1 = a1 * inv + bb.y;

    float m = fmaxf(v0, v1);
    #pragma unroll
    for (int o = 16; o; o >>= 1) m = fmaxf(m, __shfl_xor_sync(0xffffffffu, m, o));
    float s = __expf(v0 - m) + __expf(v1 - m);
    #pragma unroll
    for (int o = 16; o; o >>= 1) s += __shfl_xor_sync(0xffffffffu, s, o);
    float ls = __logf(s) + m;

    float2 st = make_float2(v0 - ls, v1 - ls);
    *reinterpret_cast<float2*>(out + (size_t)dst * GOUT + 2 * lane) = st;
}

// ---------------- launch --------------------------------------------------------
extern "C" void kernel_launch(void* const* d_in, const int* in_sizes, int n_in,
                              void* d_out, int out_size) {
    const float* x      = (const float*)d_in[0];
    const int*   ei     = (const int*)d_in[1];
    const float* W1     = (const float*)d_in[2];
    const float* a_src1 = (const float*)d_in[3];
    const float* a_dst1 = (const float*)d_in[4];
    const float* b1     = (const float*)d_in[5];
    const float* W2     = (const float*)d_in[6];
    const float* a_src2 = (const float*)d_in[7];
    const float* a_dst2 = (const float*)d_in[8];
    const float* b2     = (const float*)d_in[9];
    float* out = (float*)d_out;
    const int E = in_sizes[1] / 2;

    __nv_bfloat16 *w1p, *w2p, *h1p, *out1p, *h2p;
    float *as1p, *ad1p, *as2p, *ad2p;
    void* cntp;
    cudaGetSymbolAddress((void**)&w1p, g_w1b);
    cudaGetSymbolAddress((void**)&w2p, g_w2b);
    cudaGetSymbolAddress((void**)&h1p, g_h1b);
    cudaGetSymbolAddress((void**)&out1p, g_out1b);
    cudaGetSymbolAddress((void**)&h2p, g_h2b);
    cudaGetSymbolAddress((void**)&as1p, g_as1);
    cudaGetSymbolAddress((void**)&ad1p, g_ad1);
    cudaGetSymbolAddress((void**)&as2p, g_as2);
    cudaGetSymbolAddress((void**)&ad2p, g_ad2);
    cudaGetSymbolAddress(&cntp, g_cnt);

    // CSR build + W conversion
    cudaMemsetAsync(cntp, 0, GN * sizeof(int));
    prep_kernel<<<(E / 4 + 4 + 255) / 256, 256>>>(ei, E, W1, W2);
    block_sum_kernel<<<NB, 256>>>();
    scan_apply_kernel<<<NB, 256>>>();
    scatter_kernel<<<(E / 4 + 4 + 255) / 256, 256>>>(ei, E);

    // layer 1: fp32-A bf16 GEMM (A read once) with fused alpha1 epilogue
    gemm1_kernel<<<(GN + 63) / 64, 256>>>(x, w1p, h1p, a_src1, a_dst1, as1p, ad1p);
    agg1_kernel<<<(GN + 7) / 8, 256>>>(b1);

    // layer 2: bf16 GEMM with fused alpha2 epilogue
    gemm2_kernel<<<dim3(1, (GN + 127) / 128), 256>>>(
        out1p, w2p, h2p, GN, GF1, GOUT, a_src2, a_dst2, as2p, ad2p);
    agg2_kernel<<<(GN + 7) / 8, 256>>>(b2, out);
}

// round 8
// speedup vs baseline: 3.6682x; 1.0746x over previous
#include <cuda_runtime.h>
#include <cuda_bf16.h>
#include <cstdint>

#define GN 50000      // nodes
#define GE 800000     // edges (without self loops)
#define GIN 256       // in_dim
#define GH 8          // heads layer1
#define GHID 32       // hidden per head
#define GF1 256       // H*HID
#define GOUT 64       // classes
#define NB  ((GN + 255) / 256)

// ---------------- scratch (device globals) -------------------------------------
__device__ __nv_bfloat16 g_w1b[GIN * GF1];           // W1 bf16
__device__ __nv_bfloat16 g_w2b[GF1 * GOUT];          // W2 bf16
__device__ __nv_bfloat16 g_h1b[(size_t)GN * GF1];    // x @ W1, bf16
__device__ __nv_bfloat16 g_out1b[(size_t)GN * GF1];  // relu(gat1), bf16
__device__ __nv_bfloat16 g_h2b[(size_t)GN * GOUT];   // out1 @ W2, bf16
__device__ float g_as1[(size_t)GN * GH];
__device__ float g_ad1[(size_t)GN * GH];
__device__ float g_as2[GN];
__device__ float g_ad2[GN];
__device__ int   g_cnt[GN];        // histogram -> cursor
__device__ int   g_rowptr[GN + 1];
__device__ int   g_srcs[GE];       // src ids bucketed by dst
__device__ int   g_bsum[NB + 1];

__device__ __forceinline__ float lrelu(float x) { return fmaxf(x, 0.2f * x); }

__device__ __forceinline__ uint32_t pack_bf16x2(float lo, float hi) {
    uint32_t r;
    asm("cvt.rn.bf16x2.f32 %0, %1, %2;" : "=r"(r) : "f"(hi), "f"(lo));
    return r;
}
__device__ __forceinline__ float2 unpack_bf16x2(uint32_t u) {
    float2 f;
    f.x = __uint_as_float(u << 16);
    f.y = __uint_as_float(u & 0xffff0000u);
    return f;
}
__device__ __forceinline__ uint32_t smem_u32(const void* p) {
    return (uint32_t)__cvta_generic_to_shared(p);
}
__device__ __forceinline__ void cp_async16(uint32_t dst, const void* src, bool pred) {
    int sz = pred ? 16 : 0;
    asm volatile("cp.async.cg.shared.global [%0], [%1], 16, %2;\n"
                 :: "r"(dst), "l"(src), "r"(sz));
}
__device__ __forceinline__ void cp_commit() {
    asm volatile("cp.async.commit_group;\n");
}
__device__ __forceinline__ void ldsm_x4(uint32_t* r, uint32_t addr) {
    asm volatile("ldmatrix.sync.aligned.m8n8.x4.shared.b16 {%0,%1,%2,%3}, [%4];\n"
                 : "=r"(r[0]), "=r"(r[1]), "=r"(r[2]), "=r"(r[3]) : "r"(addr));
}
__device__ __forceinline__ void ldsm_x4_t(uint32_t* r, uint32_t addr) {
    asm volatile("ldmatrix.sync.aligned.m8n8.x4.trans.shared.b16 {%0,%1,%2,%3}, [%4];\n"
                 : "=r"(r[0]), "=r"(r[1]), "=r"(r[2]), "=r"(r[3]) : "r"(addr));
}
__device__ __forceinline__ void mma_bf16(float* c, const uint32_t* a, uint32_t b0, uint32_t b1) {
    asm volatile(
        "mma.sync.aligned.m16n8k16.row.col.f32.bf16.bf16.f32 "
        "{%0,%1,%2,%3},{%4,%5,%6,%7},{%8,%9},{%0,%1,%2,%3};\n"
        : "+f"(c[0]), "+f"(c[1]), "+f"(c[2]), "+f"(c[3])
        : "r"(a[0]), "r"(a[1]), "r"(a[2]), "r"(a[3]), "r"(b0), "r"(b1));
}

// ---------------- CSR build (side stream) --------------------------------------
__global__ void hist_kernel(const int* __restrict__ ei, int E) {
    int i = blockIdx.x * blockDim.x + threadIdx.x;
    int n4 = E >> 2;
    if (i < n4) {
        int4 d = reinterpret_cast<const int4*>(ei + E)[i];
        atomicAdd(&g_cnt[d.x], 1);
        atomicAdd(&g_cnt[d.y], 1);
        atomicAdd(&g_cnt[d.z], 1);
        atomicAdd(&g_cnt[d.w], 1);
    } else if (i < n4 + (E & 3)) {
        atomicAdd(&g_cnt[ei[E + n4 * 4 + (i - n4)]], 1);
    }
}

__global__ void block_sum_kernel() {
    __shared__ int ws[8];
    int i = blockIdx.x * 256 + threadIdx.x;
    int v = (i < GN) ? g_cnt[i] : 0;
    int s = v;
    #pragma unroll
    for (int o = 16; o; o >>= 1) s += __shfl_xor_sync(0xffffffffu, s, o);
    if ((threadIdx.x & 31) == 0) ws[threadIdx.x >> 5] = s;
    __syncthreads();
    if (threadIdx.x < 8) {
        int t = ws[threadIdx.x];
        #pragma unroll
        for (int o = 4; o; o >>= 1) t += __shfl_xor_sync(0xffu, t, o);
        if (threadIdx.x == 0) g_bsum[blockIdx.x] = t;
    }
}

__global__ void scan_apply_kernel() {
    __shared__ int ws[8];
    __shared__ int s_off;
    int tid = threadIdx.x, lane = tid & 31, wid = tid >> 5;

    int a = 0;
    for (int j = tid; j < blockIdx.x; j += 256) a += g_bsum[j];
    #pragma unroll
    for (int o = 16; o; o >>= 1) a += __shfl_xor_sync(0xffffffffu, a, o);
    if (lane == 0) ws[wid] = a;
    __syncthreads();
    if (tid == 0) {
        int t = 0;
        #pragma unroll
        for (int k = 0; k < 8; k++) t += ws[k];
        s_off = t;
    }
    __syncthreads();

    int i = blockIdx.x * 256 + tid;
    int v = (i < GN) ? g_cnt[i] : 0;
    int s = v;
    #pragma unroll
    for (int o = 1; o < 32; o <<= 1) {
        int t = __shfl_up_sync(0xffffffffu, s, o);
        if (lane >= o) s += t;
    }
    if (lane == 31) ws[wid] = s;
    __syncthreads();
    if (wid == 0 && lane < 8) {
        int t = ws[lane];
        #pragma unroll
        for (int o = 1; o < 8; o <<= 1) {
            int u = __shfl_up_sync(0xffu, t, o);
            if (lane >= o) t += u;
        }
        ws[lane] = t;
    }
    __syncthreads();
    int incl = s + (wid ? ws[wid - 1] : 0) + s_off;
    if (i < GN) {
        g_rowptr[i + 1] = incl;
        g_cnt[i] = incl - v;   // exclusive -> scatter cursor
    }
    if (i == 0) g_rowptr[0] = 0;
}

__global__ void scatter_kernel(const int* __restrict__ ei, int E) {
    int i = blockIdx.x * blockDim.x + threadIdx.x;
    int n4 = E >> 2;
    if (i < n4) {
        int4 sv = reinterpret_cast<const int4*>(ei)[i];
        int4 dv = reinterpret_cast<const int4*>(ei + E)[i];
        g_srcs[atomicAdd(&g_cnt[dv.x], 1)] = sv.x;
        g_srcs[atomicAdd(&g_cnt[dv.y], 1)] = sv.y;
        g_srcs[atomicAdd(&g_cnt[dv.z], 1)] = sv.z;
        g_srcs[atomicAdd(&g_cnt[dv.w], 1)] = sv.w;
    } else if (i < n4 + (E & 3)) {
        int e = n4 * 4 + (i - n4);
        g_srcs[atomicAdd(&g_cnt[ei[E + e]], 1)] = ei[e];
    }
}

// ---------------- W1/W2 fp32 -> bf16 (main stream, before gemm1) ---------------
__global__ void convw_kernel(const float* __restrict__ W1, const float* __restrict__ W2) {
    int i = blockIdx.x * blockDim.x + threadIdx.x;
    int stride = gridDim.x * blockDim.x;
    const int T1 = GIN * GF1 / 8;
    for (int t = i; t < T1; t += stride) {
        float4 v0 = reinterpret_cast<const float4*>(W1)[t * 2];
        float4 v1 = reinterpret_cast<const float4*>(W1)[t * 2 + 1];
        uint4 u = make_uint4(pack_bf16x2(v0.x, v0.y), pack_bf16x2(v0.z, v0.w),
                             pack_bf16x2(v1.x, v1.y), pack_bf16x2(v1.z, v1.w));
        reinterpret_cast<uint4*>(g_w1b)[t] = u;
    }
    const int T2 = GF1 * GOUT / 8;
    for (int t = i; t < T2; t += stride) {
        float4 v0 = reinterpret_cast<const float4*>(W2)[t * 2];
        float4 v1 = reinterpret_cast<const float4*>(W2)[t * 2 + 1];
        uint4 u = make_uint4(pack_bf16x2(v0.x, v0.y), pack_bf16x2(v0.z, v0.w),
                             pack_bf16x2(v1.x, v1.y), pack_bf16x2(v1.z, v1.w));
        reinterpret_cast<uint4*>(g_w2b)[t] = u;
    }
}

// ---------------- GEMM1: A fp32 (x), B bf16 (W1), BM=64 BN=256 -----------------
__global__ void __launch_bounds__(256) gemm1_kernel(
    const float* __restrict__ A, const __nv_bfloat16* __restrict__ B,
    __nv_bfloat16* __restrict__ C,
    const float* __restrict__ a_src, const float* __restrict__ a_dst,
    float* __restrict__ g_as, float* __restrict__ g_ad) {
    constexpr int BN = 256, SBS = BN + 8;
    constexpr int A_ELEM = 64 * 40;
    constexpr int B_ELEM = 32 * SBS;
    __shared__ __align__(16) __nv_bfloat16 sA[2][A_ELEM];
    __shared__ __align__(16) __nv_bfloat16 sB[2][B_ELEM];

    const int tid = threadIdx.x, lane = tid & 31, wid = tid >> 5;
    const int warpM = wid & 1, warpN = wid >> 1;      // 2 x 4
    const int rowBase = blockIdx.x * 64;
    const int wcb = warpN * 64;

    const uint32_t sAu = smem_u32(&sA[0][0]), sBu = smem_u32(&sB[0][0]);
    const int aRow = warpM * 32 + (lane & 7) + ((lane >> 3) & 1) * 8;
    const uint32_t aAddr = sAu + (uint32_t)(aRow * 40 + ((lane >> 4) * 8)) * 2;
    const int bRow = (lane & 7) + ((lane >> 3) & 1) * 8;
    const uint32_t bAddr = sBu + (uint32_t)(bRow * SBS + wcb + (lane >> 4) * 8) * 2;

    const int ar0 = tid >> 3, ac0 = (tid & 7) * 4;
    const int ar1 = (tid + 256) >> 3, ac1 = ac0;

    auto ldA = [&](float4* r, int k0) {
        int row0 = rowBase + ar0, row1 = rowBase + ar1;
        r[0] = (row0 < GN) ? *reinterpret_cast<const float4*>(A + (size_t)row0 * GIN + k0 + ac0)
                           : make_float4(0.f, 0.f, 0.f, 0.f);
        r[1] = (row1 < GN) ? *reinterpret_cast<const float4*>(A + (size_t)row1 * GIN + k0 + ac1)
                           : make_float4(0.f, 0.f, 0.f, 0.f);
    };
    auto stA = [&](int buf, const float4* r) {
        uint2 p0 = make_uint2(pack_bf16x2(r[0].x, r[0].y), pack_bf16x2(r[0].z, r[0].w));
        uint2 p1 = make_uint2(pack_bf16x2(r[1].x, r[1].y), pack_bf16x2(r[1].z, r[1].w));
        *reinterpret_cast<uint2*>(&sA[buf][ar0 * 40 + ac0]) = p0;
        *reinterpret_cast<uint2*>(&sA[buf][ar1 * 40 + ac1]) = p1;
    };
    auto stageB = [&](int buf, int k0) {
        #pragma unroll
        for (int i2 = 0; i2 < 4; i2++) {
            int f = tid + i2 * 256;
            int krow = f >> 5, c8 = (f & 31) * 8;
            uint32_t dst = sBu + (uint32_t)(buf * B_ELEM + krow * SBS + c8) * 2;
            cp_async16(dst, B + (size_t)(k0 + krow) * BN + c8, true);
        }
    };

    float c[2][8][4];
    #pragma unroll
    for (int i = 0; i < 2; i++)
        #pragma unroll
        for (int j = 0; j < 8; j++)
            #pragma unroll
            for (int q = 0; q < 4; q++) c[i][j][q] = 0.f;

    constexpr int S = GIN / 32;
    float4 ra[2];
    ldA(ra, 0);
    stA(0, ra);
    stageB(0, 0);
    cp_commit();

    float4 rn[2];
    for (int s = 0; s < S; s++) {
        const int buf = s & 1;
        if (s + 1 < S) {
            ldA(rn, (s + 1) * 32);
            stageB(buf ^ 1, (s + 1) * 32);
            cp_commit();
            asm volatile("cp.async.wait_group 1;\n");
        } else {
            asm volatile("cp.async.wait_group 0;\n");
        }
        __syncthreads();
        const uint32_t aB = aAddr + buf * A_ELEM * 2;
        const uint32_t bB = bAddr + buf * B_ELEM * 2;
        #pragma unroll
        for (int ks = 0; ks < 2; ks++) {
            uint32_t a[2][4];
            #pragma unroll
            for (int mt = 0; mt < 2; mt++)
                ldsm_x4(a[mt], aB + (uint32_t)(mt * 16 * 40 + ks * 16) * 2);
            uint32_t b[4][4];
            #pragma unroll
            for (int np = 0; np < 4; np++)
                ldsm_x4_t(b[np], bB + (uint32_t)(ks * 16 * SBS + np * 16) * 2);
            #pragma unroll
            for (int mt = 0; mt < 2; mt++)
                #pragma unroll
                for (int nt = 0; nt < 8; nt++) {
                    int np = nt >> 1;
                    mma_bf16(c[mt][nt], a[mt], b[np][(nt & 1) * 2], b[np][(nt & 1) * 2 + 1]);
                }
        }
        if (s + 1 < S) stA(buf ^ 1, rn);
        __syncthreads();
    }

    #pragma unroll
    for (int mt = 0; mt < 2; mt++)
        #pragma unroll
        for (int half = 0; half < 2; half++) {
            int row = rowBase + warpM * 32 + mt * 16 + (lane >> 2) + half * 8;
            if (row < GN) {
                #pragma unroll
                for (int nt = 0; nt < 8; nt++) {
                    int col = wcb + nt * 8 + (lane & 3) * 2;
                    uint32_t u = pack_bf16x2(c[mt][nt][half * 2], c[mt][nt][half * 2 + 1]);
                    *reinterpret_cast<uint32_t*>(C + (size_t)row * GF1 + col) = u;
                }
            }
        }

    float asc[16], adc[16];
    #pragma unroll
    for (int nt = 0; nt < 8; nt++)
        #pragma unroll
        for (int j = 0; j < 2; j++) {
            int col = wcb + nt * 8 + (lane & 3) * 2 + j;
            asc[nt * 2 + j] = a_src[col];
            adc[nt * 2 + j] = a_dst[col];
        }
    int headBase = wcb >> 5;
    #pragma unroll
    for (int mt = 0; mt < 2; mt++)
        #pragma unroll
        for (int half = 0; half < 2; half++) {
            int row = rowBase + warpM * 32 + mt * 16 + (lane >> 2) + half * 8;
            float ss0 = 0.f, ss1 = 0.f, sd0 = 0.f, sd1 = 0.f;
            #pragma unroll
            for (int nt = 0; nt < 8; nt++)
                #pragma unroll
                for (int j = 0; j < 2; j++) {
                    float v = c[mt][nt][half * 2 + j];
                    if (nt < 4) { ss0 += v * asc[nt * 2 + j]; sd0 += v * adc[nt * 2 + j]; }
                    else        { ss1 += v * asc[nt * 2 + j]; sd1 += v * adc[nt * 2 + j]; }
                }
            #pragma unroll
            for (int o = 1; o <= 2; o <<= 1) {
                ss0 += __shfl_xor_sync(0xffffffffu, ss0, o);
                ss1 += __shfl_xor_sync(0xffffffffu, ss1, o);
                sd0 += __shfl_xor_sync(0xffffffffu, sd0, o);
                sd1 += __shfl_xor_sync(0xffffffffu, sd1, o);
            }
            if ((lane & 3) == 0 && row < GN) {
                g_as[(size_t)row * GH + headBase]     = ss0;
                g_as[(size_t)row * GH + headBase + 1] = ss1;
                g_ad[(size_t)row * GH + headBase]     = sd0;
                g_ad[(size_t)row * GH + headBase + 1] = sd1;
            }
        }
}

// ---------------- GEMM2: bf16 A (out1), BN=64, fused alpha2 --------------------
__global__ void __launch_bounds__(256) gemm2_kernel(
    const __nv_bfloat16* __restrict__ A, const __nv_bfloat16* __restrict__ B,
    __nv_bfloat16* __restrict__ C, int M, int K, int Nc,
    const float* __restrict__ a_src, const float* __restrict__ a_dst,
    float* __restrict__ g_as, float* __restrict__ g_ad) {
    constexpr int BN = 64, NT = 4, NP = 2, SBS = BN + 8;
    constexpr int A_ELEM = 128 * 40;
    constexpr int B_ELEM = 32 * SBS;
    __shared__ __align__(16) __nv_bfloat16 sA[2][A_ELEM];
    __shared__ __align__(16) __nv_bfloat16 sB[2][B_ELEM];

    const int tid = threadIdx.x, lane = tid & 31, wid = tid >> 5;
    const int warpM = wid & 3, warpN = wid >> 2;
    const int rowBase = blockIdx.y * 128;
    const int wcb = warpN * (BN / 2);

    const uint32_t sAu = smem_u32(&sA[0][0]), sBu = smem_u32(&sB[0][0]);
    const int aRow = warpM * 32 + (lane & 7) + ((lane >> 3) & 1) * 8;
    const uint32_t aAddr = sAu + (uint32_t)(aRow * 40 + ((lane >> 4) * 8)) * 2;
    const int bRow = (lane & 7) + ((lane >> 3) & 1) * 8;
    const uint32_t bAddr = sBu + (uint32_t)(bRow * SBS + wcb + (lane >> 4) * 8) * 2;

    auto stageA = [&](int buf, int k0) {
        #pragma unroll
        for (int i2 = 0; i2 < 2; i2++) {
            int f = tid + i2 * 256;
            int r = f >> 2, c8 = (f & 3) * 8;
            int row = rowBase + r;
            uint32_t dst = sAu + (uint32_t)(buf * A_ELEM + r * 40 + c8) * 2;
            cp_async16(dst, A + (size_t)row * K + k0 + c8, row < M);
        }
    };
    auto stageB = [&](int buf, int k0) {
        int krow = tid >> 3, c8 = (tid & 7) * 8;
        uint32_t dst = sBu + (uint32_t)(buf * B_ELEM + krow * SBS + c8) * 2;
        cp_async16(dst, B + (size_t)(k0 + krow) * Nc + c8, true);
    };

    float c[2][NT][4];
    #pragma unroll
    for (int i = 0; i < 2; i++)
        #pragma unroll
        for (int j = 0; j < NT; j++)
            #pragma unroll
            for (int q = 0; q < 4; q++) c[i][j][q] = 0.f;

    const int S = K / 32;
    stageA(0, 0);
    stageB(0, 0);
    cp_commit();

    for (int s = 0; s < S; s++) {
        const int buf = s & 1;
        if (s + 1 < S) {
            stageA(buf ^ 1, (s + 1) * 32);
            stageB(buf ^ 1, (s + 1) * 32);
            cp_commit();
            asm volatile("cp.async.wait_group 1;\n");
        } else {
            asm volatile("cp.async.wait_group 0;\n");
        }
        __syncthreads();
        const uint32_t aB = aAddr + buf * A_ELEM * 2;
        const uint32_t bB = bAddr + buf * B_ELEM * 2;
        #pragma unroll
        for (int ks = 0; ks < 2; ks++) {
            uint32_t a[2][4];
            #pragma unroll
            for (int mt = 0; mt < 2; mt++)
                ldsm_x4(a[mt], aB + (uint32_t)(mt * 16 * 40 + ks * 16) * 2);
            uint32_t b[NP][4];
            #pragma unroll
            for (int np = 0; np < NP; np++)
                ldsm_x4_t(b[np], bB + (uint32_t)(ks * 16 * SBS + np * 16) * 2);
            #pragma unroll
            for (int mt = 0; mt < 2; mt++)
                #pragma unroll
                for (int nt = 0; nt < NT; nt++) {
                    int np = nt >> 1;
                    mma_bf16(c[mt][nt], a[mt], b[np][(nt & 1) * 2], b[np][(nt & 1) * 2 + 1]);
                }
        }
        __syncthreads();
    }

    #pragma unroll
    for (int mt = 0; mt < 2; mt++)
        #pragma unroll
        for (int half = 0; half < 2; half++) {
            int row = rowBase + warpM * 32 + mt * 16 + (lane >> 2) + half * 8;
            if (row < M) {
                #pragma unroll
                for (int nt = 0; nt < NT; nt++) {
                    int col = wcb + nt * 8 + (lane & 3) * 2;
                    uint32_t u = pack_bf16x2(c[mt][nt][half * 2], c[mt][nt][half * 2 + 1]);
                    *reinterpret_cast<uint32_t*>(C + (size_t)row * Nc + col) = u;
                }
            }
        }

    float* sP = reinterpret_cast<float*>(&sA[0][0]);   // [128][4]
    __syncthreads();
    float asc[NT * 2], adc[NT * 2];
    #pragma unroll
    for (int nt = 0; nt < NT; nt++)
        #pragma unroll
        for (int j = 0; j < 2; j++) {
            int col = wcb + nt * 8 + (lane & 3) * 2 + j;
            asc[nt * 2 + j] = a_src[col];
            adc[nt * 2 + j] = a_dst[col];
        }
    #pragma unroll
    for (int mt = 0; mt < 2; mt++)
        #pragma unroll
        for (int half = 0; half < 2; half++) {
            float ss = 0.f, sd = 0.f;
            #pragma unroll
            for (int nt = 0; nt < NT; nt++)
                #pragma unroll
                for (int j = 0; j < 2; j++) {
                    float v = c[mt][nt][half * 2 + j];
                    ss += v * asc[nt * 2 + j];
                    sd += v * adc[nt * 2 + j];
                }
            #pragma unroll
            for (int o = 1; o <= 2; o <<= 1) {
                ss += __shfl_xor_sync(0xffffffffu, ss, o);
                sd += __shfl_xor_sync(0xffffffffu, sd, o);
            }
            if ((lane & 3) == 0) {
                int rl = warpM * 32 + mt * 16 + (lane >> 2) + half * 8;
                sP[rl * 4 + warpN * 2 + 0] = ss;
                sP[rl * 4 + warpN * 2 + 1] = sd;
            }
        }
    __syncthreads();
    if (tid < 128) {
        int row = rowBase + tid;
        if (row < M) {
            g_as[row] = sP[tid * 4 + 0] + sP[tid * 4 + 2];
            g_ad[row] = sP[tid * 4 + 1] + sP[tid * 4 + 3];
        }
    }
}

// ---------------- layer-1 aggregation (warp per dst, pipelined) ----------------
__global__ void __launch_bounds__(256) agg1_kernel(const float* __restrict__ b1) {
    int dst = (blockIdx.x * blockDim.x + threadIdx.x) >> 5;
    int lane = threadIdx.x & 31;
    if (dst >= GN) return;
    const int head = lane >> 2;

    const float ad = g_ad1[(size_t)dst * GH + head];
    const int rs = g_rowptr[dst];
    const int re = g_rowptr[dst + 1];

    int src0 = (rs < re) ? g_srcs[rs] : 0;
    uint4 u = *reinterpret_cast<const uint4*>(g_h1b + (size_t)src0 * GF1 + lane * 8);
    float av = g_as1[(size_t)src0 * GH + head];

    float acc[8];
    float den;
    {   // self loop
        float w = __expf(lrelu(g_as1[(size_t)dst * GH + head] + ad));
        den = w;
        uint4 us = *reinterpret_cast<const uint4*>(g_h1b + (size_t)dst * GF1 + lane * 8);
        float2 f0 = unpack_bf16x2(us.x), f1 = unpack_bf16x2(us.y);
        float2 f2 = unpack_bf16x2(us.z), f3 = unpack_bf16x2(us.w);
        acc[0] = w * f0.x; acc[1] = w * f0.y; acc[2] = w * f1.x; acc[3] = w * f1.y;
        acc[4] = w * f2.x; acc[5] = w * f2.y; acc[6] = w * f3.x; acc[7] = w * f3.y;
    }
    for (int e = rs; e < re; e++) {
        uint4 uc = u;
        float ac = av;
        if (e + 1 < re) {
            int s2 = g_srcs[e + 1];
            u = *reinterpret_cast<const uint4*>(g_h1b + (size_t)s2 * GF1 + lane * 8);
            av = g_as1[(size_t)s2 * GH + head];
        }
        float w = __expf(lrelu(ac + ad));
        den += w;
        float2 f0 = unpack_bf16x2(uc.x), f1 = unpack_bf16x2(uc.y);
        float2 f2 = unpack_bf16x2(uc.z), f3 = unpack_bf16x2(uc.w);
        acc[0] += w * f0.x; acc[1] += w * f0.y; acc[2] += w * f1.x; acc[3] += w * f1.y;
        acc[4] += w * f2.x; acc[5] += w * f2.y; acc[6] += w * f3.x; acc[7] += w * f3.y;
    }
    float inv = 1.f / den;
    float4 bb0 = *reinterpret_cast<const float4*>(b1 + lane * 8);
    float4 bb1 = *reinterpret_cast<const float4*>(b1 + lane * 8 + 4);
    float bv[8] = {bb0.x, bb0.y, bb0.z, bb0.w, bb1.x, bb1.y, bb1.z, bb1.w};
    uint4 st;
    uint32_t* stp = reinterpret_cast<uint32_t*>(&st);
    #pragma unroll
    for (int p = 0; p < 4; p++) {
        float v0 = fmaxf(acc[2 * p] * inv + bv[2 * p], 0.f);
        float v1 = fmaxf(acc[2 * p + 1] * inv + bv[2 * p + 1], 0.f);
        stp[p] = pack_bf16x2(v0, v1);
    }
    *reinterpret_cast<uint4*>(g_out1b + (size_t)dst * GF1 + lane * 8) = st;
}

// ---------------- layer-2 aggregation + bias + log_softmax ---------------------
__global__ void __launch_bounds__(256) agg2_kernel(const float* __restrict__ b2,
                                                   float* __restrict__ out) {
    int dst = (blockIdx.x * blockDim.x + threadIdx.x) >> 5;
    int lane = threadIdx.x & 31;
    if (dst >= GN) return;

    const float ad = g_ad2[dst];
    const int rs = g_rowptr[dst];
    const int re = g_rowptr[dst + 1];

    int src0 = (rs < re) ? g_srcs[rs] : 0;
    uint32_t u = *reinterpret_cast<const uint32_t*>(g_h2b + (size_t)src0 * GOUT + 2 * lane);
    float av = g_as2[src0];

    float den, a0, a1;
    {
        float w = __expf(lrelu(g_as2[dst] + ad));
        den = w;
        uint32_t us = *reinterpret_cast<const uint32_t*>(g_h2b + (size_t)dst * GOUT + 2 * lane);
        float2 f = unpack_bf16x2(us);
        a0 = w * f.x;
        a1 = w * f.y;
    }
    for (int e = rs; e < re; e++) {
        uint32_t uc = u;
        float ac = av;
        if (e + 1 < re) {
            int s2 = g_srcs[e + 1];
            u = *reinterpret_cast<const uint32_t*>(g_h2b + (size_t)s2 * GOUT + 2 * lane);
            av = g_as2[s2];
        }
        float w = __expf(lrelu(ac + ad));
        den += w;
        float2 f = unpack_bf16x2(uc);
        a0 += w * f.x;
        a1 += w * f.y;
    }
    float2 bb = *reinterpret_cast<const float2*>(b2 + 2 * lane);
    float inv = 1.f / den;
    float v0 = a0 * inv + bb.x;
    float v1 = a1 * inv + bb.y;

    float m = fmaxf(v0, v1);
    #pragma unroll
    for (int o = 16; o; o >>= 1) m = fmaxf(m, __shfl_xor_sync(0xffffffffu, m, o));
    float s = __expf(v0 - m) + __expf(v1 - m);
    #pragma unroll
    for (int o = 16; o; o >>= 1) s += __shfl_xor_sync(0xffffffffu, s, o);
    float ls = __logf(s) + m;

    float2 st = make_float2(v0 - ls, v1 - ls);
    *reinterpret_cast<float2*>(out + (size_t)dst * GOUT + 2 * lane) = st;
}

// ---------------- launch --------------------------------------------------------
extern "C" void kernel_launch(void* const* d_in, const int* in_sizes, int n_in,
                              void* d_out, int out_size) {
    const float* x      = (const float*)d_in[0];
    const int*   ei     = (const int*)d_in[1];
    const float* W1     = (const float*)d_in[2];
    const float* a_src1 = (const float*)d_in[3];
    const float* a_dst1 = (const float*)d_in[4];
    const float* b1     = (const float*)d_in[5];
    const float* W2     = (const float*)d_in[6];
    const float* a_src2 = (const float*)d_in[7];
    const float* a_dst2 = (const float*)d_in[8];
    const float* b2     = (const float*)d_in[9];
    float* out = (float*)d_out;
    const int E = in_sizes[1] / 2;

    __nv_bfloat16 *w1p, *w2p, *h1p, *out1p, *h2p;
    float *as1p, *ad1p, *as2p, *ad2p;
    void* cntp;
    cudaGetSymbolAddress((void**)&w1p, g_w1b);
    cudaGetSymbolAddress((void**)&w2p, g_w2b);
    cudaGetSymbolAddress((void**)&h1p, g_h1b);
    cudaGetSymbolAddress((void**)&out1p, g_out1b);
    cudaGetSymbolAddress((void**)&h2p, g_h2b);
    cudaGetSymbolAddress((void**)&as1p, g_as1);
    cudaGetSymbolAddress((void**)&ad1p, g_ad1);
    cudaGetSymbolAddress((void**)&as2p, g_as2);
    cudaGetSymbolAddress((void**)&ad2p, g_ad2);
    cudaGetSymbolAddress(&cntp, g_cnt);

    // side stream + fork/join events (host resources, created once, no device mem)
    static cudaStream_t s_side = nullptr;
    static cudaEvent_t s_fork = nullptr, s_join = nullptr;
    if (s_side == nullptr) {
        cudaStreamCreateWithFlags(&s_side, cudaStreamNonBlocking);
        cudaEventCreateWithFlags(&s_fork, cudaEventDisableTiming);
        cudaEventCreateWithFlags(&s_join, cudaEventDisableTiming);
    }

    // fork: CSR chain on side stream, GEMM1 chain on main stream
    cudaEventRecord(s_fork, 0);
    cudaStreamWaitEvent(s_side, s_fork, 0);

    // --- side: CSR build
    cudaMemsetAsync(cntp, 0, GN * sizeof(int), s_side);
    hist_kernel<<<(E / 4 + 4 + 255) / 256, 256, 0, s_side>>>(ei, E);
    block_sum_kernel<<<NB, 256, 0, s_side>>>();
    scan_apply_kernel<<<NB, 256, 0, s_side>>>();
    scatter_kernel<<<(E / 4 + 4 + 255) / 256, 256, 0, s_side>>>(ei, E);
    cudaEventRecord(s_join, s_side);

    // --- main: W conversion + GEMM1 (+ fused alpha1)
    convw_kernel<<<132, 256>>>(W1, W2);
    gemm1_kernel<<<(GN + 63) / 64, 256>>>(x, w1p, h1p, a_src1, a_dst1, as1p, ad1p);

    // join
    cudaStreamWaitEvent(0, s_join, 0);

    agg1_kernel<<<(GN + 7) / 8, 256>>>(b1);
    gemm2_kernel<<<dim3(1, (GN + 127) / 128), 256>>>(
        out1p, w2p, h2p, GN, GF1, GOUT, a_src2, a_dst2, as2p, ad2p);
    agg2_kernel<<<(GN + 7) / 8, 256>>>(b2, out);
}